// round 12
// baseline (speedup 1.0000x reference)
#include <cuda_runtime.h>
#include <cuda_fp16.h>
#include <cstdint>

#define N_USERS 100000
#define N_ITEMS 50000
#define N_NODESC 150000
#define NNZC 2400000
#define DIM 64
#define BATCHC 4096
#define HALFC 4800000u
#define NPAIR 75000
#define EPSC 0.1f
#define INV_TEMP 5.0f

// ---------------- static device scratch (allocation-free) ----------------
__device__ float  g_e1 [N_NODESC * DIM];
__device__ float  g_e2 [N_NODESC * DIM];
__device__ uint2  g_d1 [N_NODESC * 32];   // half4 noise offsets (v1x,v1y,v2x,v2y) at [row*32+lane]
__device__ uint2  g_d2 [N_NODESC * 32];   // layer-2 view delta = A*d1 + noise2 offsets
__device__ int2   g_cv[NNZC];
__device__ int    g_rowptr[N_NODESC + 1];
__device__ int    g_cursor[N_NODESC];
__device__ int    g_counts[N_NODESC];
__device__ int    g_blocksums[256];
__device__ int    g_flags[N_NODESC];
__device__ int    g_uidx[BATCHC];
__device__ int    g_iidx[BATCHC];
__device__ int    g_ucnt;
__device__ int    g_icnt;
__device__ float  g_V1u[BATCHC * DIM], g_V2u[BATCHC * DIM];
__device__ float  g_V1i[BATCHC * DIM], g_V2i[BATCHC * DIM];
__device__ float  g_posU[BATCHC], g_posI[BATCHC];
__device__ float  g_S[2 * BATCHC];
__device__ float  g_acc[8];               // 0 rec, 1 ssu, 2 ssp, 3 nceU, 4 nceI

// ---------------- half4 pack/unpack ----------------
__device__ __forceinline__ uint2 pack4h(float a, float b, float c, float d) {
    __half2 lo = __floats2half2_rn(a, b);
    __half2 hi = __floats2half2_rn(c, d);
    uint2 r;
    r.x = *(const unsigned*)&lo;
    r.y = *(const unsigned*)&hi;
    return r;
}
__device__ __forceinline__ float4 unpack4h(uint2 u) {
    float2 lo = __half22float2(*(const __half2*)&u.x);
    float2 hi = __half22float2(*(const __half2*)&u.y);
    return make_float4(lo.x, lo.y, hi.x, hi.y);
}

// ---------------- threefry-2x32 (exact JAX schedule) ----------------
__host__ __device__ __forceinline__ unsigned rl32(unsigned x, int r) {
    return (x << r) | (x >> (32 - r));
}
__host__ __device__ __forceinline__ void tf2x32(unsigned k0, unsigned k1,
                                                unsigned x0, unsigned x1,
                                                unsigned& o0, unsigned& o1) {
    unsigned k2 = k0 ^ k1 ^ 0x1BD11BDAu;
    x0 += k0; x1 += k1;
#define TFR(r) { x0 += x1; x1 = rl32(x1, r); x1 ^= x0; }
    TFR(13) TFR(15) TFR(26) TFR(6)
    x0 += k1; x1 += k2 + 1u;
    TFR(17) TFR(29) TFR(16) TFR(24)
    x0 += k2; x1 += k0 + 2u;
    TFR(13) TFR(15) TFR(26) TFR(6)
    x0 += k0; x1 += k1 + 3u;
    TFR(17) TFR(29) TFR(16) TFR(24)
    x0 += k1; x1 += k2 + 4u;
    TFR(13) TFR(15) TFR(26) TFR(6)
    x0 += k2; x1 += k0 + 5u;
#undef TFR
    o0 = x0; o1 = x1;
}
__device__ __forceinline__ float u32_to_unit(unsigned b) {
    return __uint_as_float((b >> 9) | 0x3f800000u) - 1.0f;
}
__device__ __forceinline__ float wredsum(float v) {
#pragma unroll
    for (int o = 16; o; o >>= 1) v += __shfl_xor_sync(0xffffffffu, v, o);
    return v;
}
__device__ __forceinline__ float sgn(float x) {
    return (x > 0.f) ? 1.f : ((x < 0.f) ? -1.f : 0.f);
}
// FMA-only exp for x in [-15, 0]: 2^(x*log2e) with degree-6 Taylor of 2^f
__device__ __forceinline__ float fexp(float x) {
    float t = x * 1.4426950408889634f;
    float fi = floorf(t);
    float f = t - fi;
    float p = 1.5404e-4f;
    p = fmaf(p, f, 1.3333558e-3f);
    p = fmaf(p, f, 9.6181291e-3f);
    p = fmaf(p, f, 5.5504109e-2f);
    p = fmaf(p, f, 2.4022651e-1f);
    p = fmaf(p, f, 6.9314718e-1f);
    p = fmaf(p, f, 1.0f);
    return __int_as_float(((int)fi + 127) << 23) * p;
}

// per-row noise for standalone rows (vfinal only, ~8K rows)
__device__ __forceinline__ void row_noise(int row, int lane, unsigned k0, unsigned k1,
                                          float& nx, float& ny, float& sc) {
    int half = (row >= NPAIR);
    unsigned base = (unsigned)(half ? row - NPAIR : row) * 64u + (unsigned)(lane * 2);
    unsigned a0, a1, b0, b1;
    tf2x32(k0, k1, base, base + HALFC, a0, a1);
    tf2x32(k0, k1, base + 1u, base + 1u + HALFC, b0, b1);
    nx = u32_to_unit(half ? a1 : a0);
    ny = u32_to_unit(half ? b1 : b0);
    sc = EPSC * rsqrtf(wredsum(nx * nx + ny * ny));
}

// warp computes one CSR row (float2 source); 4-wide MLP
__device__ __forceinline__ float2 csr_row(const float* __restrict__ x, int row, int lane) {
    int s = g_rowptr[row], e = g_rowptr[row + 1];
    float ax = 0.f, ay = 0.f, bx = 0.f, by = 0.f;
    float cx = 0.f, cy = 0.f, dx = 0.f, dy = 0.f;
    int i = s;
    for (; i + 3 < e; i += 4) {
        int2 c0 = g_cv[i], c1 = g_cv[i + 1], c2 = g_cv[i + 2], c3 = g_cv[i + 3];
        float2 p0 = ((const float2*)(x + (c0.x << 6)))[lane];
        float2 p1 = ((const float2*)(x + (c1.x << 6)))[lane];
        float2 p2 = ((const float2*)(x + (c2.x << 6)))[lane];
        float2 p3 = ((const float2*)(x + (c3.x << 6)))[lane];
        float v0 = __int_as_float(c0.y), v1 = __int_as_float(c1.y);
        float v2 = __int_as_float(c2.y), v3 = __int_as_float(c3.y);
        ax = fmaf(v0, p0.x, ax); ay = fmaf(v0, p0.y, ay);
        bx = fmaf(v1, p1.x, bx); by = fmaf(v1, p1.y, by);
        cx = fmaf(v2, p2.x, cx); cy = fmaf(v2, p2.y, cy);
        dx = fmaf(v3, p3.x, dx); dy = fmaf(v3, p3.y, dy);
    }
    for (; i < e; i++) {
        int2 c0 = g_cv[i];
        float2 p0 = ((const float2*)(x + (c0.x << 6)))[lane];
        float v0 = __int_as_float(c0.y);
        ax = fmaf(v0, p0.x, ax); ay = fmaf(v0, p0.y, ay);
    }
    return make_float2((ax + bx) + (cx + dx), (ay + by) + (cy + dy));
}

// layer-1 gather directly from the two input embedding arrays
__device__ __forceinline__ float2 csr_row_in(const float* __restrict__ ue,
                                             const float* __restrict__ ie,
                                             int row, int lane) {
    int s = g_rowptr[row], e = g_rowptr[row + 1];
    float ax = 0.f, ay = 0.f, bx = 0.f, by = 0.f;
    float cx = 0.f, cy = 0.f, dx = 0.f, dy = 0.f;
    int i = s;
#define SRC(c) ((c) < N_USERS ? ue + ((c) << 6) : ie + (((c) - N_USERS) << 6))
    for (; i + 3 < e; i += 4) {
        int2 c0 = g_cv[i], c1 = g_cv[i + 1], c2 = g_cv[i + 2], c3 = g_cv[i + 3];
        float2 p0 = ((const float2*)SRC(c0.x))[lane];
        float2 p1 = ((const float2*)SRC(c1.x))[lane];
        float2 p2 = ((const float2*)SRC(c2.x))[lane];
        float2 p3 = ((const float2*)SRC(c3.x))[lane];
        float v0 = __int_as_float(c0.y), v1 = __int_as_float(c1.y);
        float v2 = __int_as_float(c2.y), v3 = __int_as_float(c3.y);
        ax = fmaf(v0, p0.x, ax); ay = fmaf(v0, p0.y, ay);
        bx = fmaf(v1, p1.x, bx); by = fmaf(v1, p1.y, by);
        cx = fmaf(v2, p2.x, cx); cy = fmaf(v2, p2.y, cy);
        dx = fmaf(v3, p3.x, dx); dy = fmaf(v3, p3.y, dy);
    }
    for (; i < e; i++) {
        int2 c0 = g_cv[i];
        float2 p0 = ((const float2*)SRC(c0.x))[lane];
        float v0 = __int_as_float(c0.y);
        ax = fmaf(v0, p0.x, ax); ay = fmaf(v0, p0.y, ay);
    }
#undef SRC
    return make_float2((ax + bx) + (cx + dx), (ay + by) + (cy + dy));
}

// one CSR pass over e1 (float2) + d1 (half4): se = A*e1, sd = A*d1
__device__ __forceinline__ void csr_row_l2(int row, int lane, float2& se, float4& sd) {
    int s = g_rowptr[row], e = g_rowptr[row + 1];
    float ex0 = 0.f, ey0 = 0.f, ex1 = 0.f, ey1 = 0.f;
    float dx0 = 0.f, dy0 = 0.f, dz0 = 0.f, dw0 = 0.f;
    float dx1 = 0.f, dy1 = 0.f, dz1 = 0.f, dw1 = 0.f;
    int i = s;
    for (; i + 3 < e; i += 4) {
        int2 c0 = g_cv[i], c1 = g_cv[i + 1], c2 = g_cv[i + 2], c3 = g_cv[i + 3];
        float2 q0 = ((const float2*)(g_e1 + (c0.x << 6)))[lane];
        float2 q1 = ((const float2*)(g_e1 + (c1.x << 6)))[lane];
        float2 q2 = ((const float2*)(g_e1 + (c2.x << 6)))[lane];
        float2 q3 = ((const float2*)(g_e1 + (c3.x << 6)))[lane];
        uint2 u0 = g_d1[(c0.x << 5) + lane];
        uint2 u1 = g_d1[(c1.x << 5) + lane];
        uint2 u2 = g_d1[(c2.x << 5) + lane];
        uint2 u3 = g_d1[(c3.x << 5) + lane];
        float v0 = __int_as_float(c0.y), v1 = __int_as_float(c1.y);
        float v2 = __int_as_float(c2.y), v3 = __int_as_float(c3.y);
        float4 p0 = unpack4h(u0), p1 = unpack4h(u1), p2 = unpack4h(u2), p3 = unpack4h(u3);
        ex0 = fmaf(v0, q0.x, ex0); ey0 = fmaf(v0, q0.y, ey0);
        ex1 = fmaf(v1, q1.x, ex1); ey1 = fmaf(v1, q1.y, ey1);
        ex0 = fmaf(v2, q2.x, ex0); ey0 = fmaf(v2, q2.y, ey0);
        ex1 = fmaf(v3, q3.x, ex1); ey1 = fmaf(v3, q3.y, ey1);
        dx0 = fmaf(v0, p0.x, dx0); dy0 = fmaf(v0, p0.y, dy0);
        dz0 = fmaf(v0, p0.z, dz0); dw0 = fmaf(v0, p0.w, dw0);
        dx1 = fmaf(v1, p1.x, dx1); dy1 = fmaf(v1, p1.y, dy1);
        dz1 = fmaf(v1, p1.z, dz1); dw1 = fmaf(v1, p1.w, dw1);
        dx0 = fmaf(v2, p2.x, dx0); dy0 = fmaf(v2, p2.y, dy0);
        dz0 = fmaf(v2, p2.z, dz0); dw0 = fmaf(v2, p2.w, dw0);
        dx1 = fmaf(v3, p3.x, dx1); dy1 = fmaf(v3, p3.y, dy1);
        dz1 = fmaf(v3, p3.z, dz1); dw1 = fmaf(v3, p3.w, dw1);
    }
    for (; i < e; i++) {
        int2 c0 = g_cv[i];
        float2 q0 = ((const float2*)(g_e1 + (c0.x << 6)))[lane];
        float4 p0 = unpack4h(g_d1[(c0.x << 5) + lane]);
        float v0 = __int_as_float(c0.y);
        ex0 = fmaf(v0, q0.x, ex0); ey0 = fmaf(v0, q0.y, ey0);
        dx0 = fmaf(v0, p0.x, dx0); dy0 = fmaf(v0, p0.y, dy0);
        dz0 = fmaf(v0, p0.z, dz0); dw0 = fmaf(v0, p0.w, dw0);
    }
    se = make_float2(ex0 + ex1, ey0 + ey1);
    sd = make_float4(dx0 + dx1, dy0 + dy1, dz0 + dz1, dw0 + dw1);
}

// layer-3 view gather: A*(e2 + d2) for one row, both views
__device__ __forceinline__ float4 csr_row_l3(int row, int lane) {
    int s = g_rowptr[row], e = g_rowptr[row + 1];
    float ax = 0.f, ay = 0.f, az = 0.f, aw = 0.f;
    float bx = 0.f, by = 0.f, bz = 0.f, bw = 0.f;
    int i = s;
    for (; i + 1 < e; i += 2) {
        int2 c0 = g_cv[i], c1 = g_cv[i + 1];
        float2 q0 = ((const float2*)(g_e2 + (c0.x << 6)))[lane];
        float2 q1 = ((const float2*)(g_e2 + (c1.x << 6)))[lane];
        float4 p0 = unpack4h(g_d2[(c0.x << 5) + lane]);
        float4 p1 = unpack4h(g_d2[(c1.x << 5) + lane]);
        float v0 = __int_as_float(c0.y), v1 = __int_as_float(c1.y);
        ax = fmaf(v0, q0.x + p0.x, ax); ay = fmaf(v0, q0.y + p0.y, ay);
        az = fmaf(v0, q0.x + p0.z, az); aw = fmaf(v0, q0.y + p0.w, aw);
        bx = fmaf(v1, q1.x + p1.x, bx); by = fmaf(v1, q1.y + p1.y, by);
        bz = fmaf(v1, q1.x + p1.z, bz); bw = fmaf(v1, q1.y + p1.w, bw);
    }
    if (i < e) {
        int2 c0 = g_cv[i];
        float2 q0 = ((const float2*)(g_e2 + (c0.x << 6)))[lane];
        float4 p0 = unpack4h(g_d2[(c0.x << 5) + lane]);
        float v0 = __int_as_float(c0.y);
        ax = fmaf(v0, q0.x + p0.x, ax); ay = fmaf(v0, q0.y + p0.y, ay);
        az = fmaf(v0, q0.x + p0.z, az); aw = fmaf(v0, q0.y + p0.w, aw);
    }
    return make_float4(ax + bx, ay + by, az + bz, aw + bw);
}

// ---------------- setup ----------------
__global__ void k_init() {
    int i = blockIdx.x * blockDim.x + threadIdx.x;
    if (i < N_NODESC) { g_flags[i] = 0; g_counts[i] = 0; }
    if (i < 2 * BATCHC) g_S[i] = 0.f;
    if (i < 8) g_acc[i] = 0.f;
    if (i == 0) { g_ucnt = 0; g_icnt = 0; }
}
__global__ void k_hist(const int* __restrict__ rows) {
    int i = blockIdx.x * blockDim.x + threadIdx.x;
    if (i < NNZC) atomicAdd(&g_counts[rows[i]], 1);
}
__global__ void k_scan1() {
    __shared__ int sh[1024];
    int g = blockIdx.x * 1024 + threadIdx.x;
    int v = (g < N_NODESC) ? g_counts[g] : 0;
    sh[threadIdx.x] = v;
    __syncthreads();
    for (int off = 1; off < 1024; off <<= 1) {
        int t = (threadIdx.x >= off) ? sh[threadIdx.x - off] : 0;
        __syncthreads();
        sh[threadIdx.x] += t;
        __syncthreads();
    }
    if (g < N_NODESC) g_rowptr[g] = sh[threadIdx.x] - v;
    if (threadIdx.x == 1023) g_blocksums[blockIdx.x] = sh[1023];
}
__global__ void k_scan2(int nblocks) {
    __shared__ int sh[256];
    int t = threadIdx.x;
    int v = (t < nblocks) ? g_blocksums[t] : 0;
    sh[t] = v;
    __syncthreads();
    for (int off = 1; off < 256; off <<= 1) {
        int p = (t >= off) ? sh[t - off] : 0;
        __syncthreads();
        sh[t] += p;
        __syncthreads();
    }
    if (t < nblocks) g_blocksums[t] = sh[t] - v;   // exclusive
    if (t == nblocks - 1) g_rowptr[N_NODESC] = sh[t];
}
__global__ void k_scan3() {
    int g = blockIdx.x * blockDim.x + threadIdx.x;
    if (g < N_NODESC) {
        int v = g_rowptr[g] + g_blocksums[g >> 10];
        g_rowptr[g] = v;
        g_cursor[g] = v;
    }
}
__global__ void k_fill(const int* __restrict__ rows, const int* __restrict__ cols,
                       const float* __restrict__ vals) {
    int i = blockIdx.x * blockDim.x + threadIdx.x;
    if (i < NNZC) {
        int p = atomicAdd(&g_cursor[rows[i]], 1);
        g_cv[p] = make_int2(cols[i], __float_as_int(vals[i]));
    }
}

// ---------------- layer 1: e1 = A*[ue;ie]; d1 = fp16 noise offsets (paired tf) ----------------
__global__ void __launch_bounds__(256) k_spmm_e1_noise(const float* __restrict__ ue,
                                                       const float* __restrict__ ie,
                                                       unsigned f10, unsigned f11,
                                                       unsigned f20, unsigned f21) {
    int warp = threadIdx.x >> 5;
    int lane = threadIdx.x & 31;
    int sub = warp & 3;
    int hi = warp >> 2;
    int pr = blockIdx.x * 4 + sub;
    int row = pr + hi * NPAIR;
    __shared__ unsigned shn[2][4][32][2];
    float2 ea = csr_row_in(ue, ie, row, lane);
    unsigned myx[2], myy[2];
    if (!hi) {
        unsigned base = (unsigned)pr * 64u + (unsigned)(lane * 2);
#pragma unroll
        for (int vv = 0; vv < 2; vv++) {
            unsigned k0 = vv ? f20 : f10, k1 = vv ? f21 : f11;
            unsigned a0, a1, b0, b1;
            tf2x32(k0, k1, base, base + HALFC, a0, a1);
            tf2x32(k0, k1, base + 1u, base + 1u + HALFC, b0, b1);
            myx[vv] = a0; myy[vv] = b0;
            shn[vv][sub][lane][0] = a1;
            shn[vv][sub][lane][1] = b1;
        }
    }
    __syncthreads();
    if (hi) {
#pragma unroll
        for (int vv = 0; vv < 2; vv++) {
            myx[vv] = shn[vv][sub][lane][0];
            myy[vv] = shn[vv][sub][lane][1];
        }
    }
    ((float2*)(g_e1 + (row << 6)))[lane] = ea;
    float o1x, o1y, o2x, o2y;
    {
        float nx = u32_to_unit(myx[0]), ny = u32_to_unit(myy[0]);
        float sc = EPSC * rsqrtf(wredsum(nx * nx + ny * ny));
        o1x = sgn(ea.x) * nx * sc;
        o1y = sgn(ea.y) * ny * sc;
    }
    {
        float nx = u32_to_unit(myx[1]), ny = u32_to_unit(myy[1]);
        float sc = EPSC * rsqrtf(wredsum(nx * nx + ny * ny));
        o2x = sgn(ea.x) * nx * sc;
        o2y = sgn(ea.y) * ny * sc;
    }
    g_d1[(row << 5) + lane] = pack4h(o1x, o1y, o2x, o2y);
}

// ---------------- layer 2: e2 = A*e1; d2 = A*d1 + noise2 offsets (paired tf) ----------------
__global__ void __launch_bounds__(256) k_spmm_l2(unsigned f10, unsigned f11,
                                                 unsigned f20, unsigned f21) {
    int warp = threadIdx.x >> 5;
    int lane = threadIdx.x & 31;
    int sub = warp & 3;
    int hi = warp >> 2;
    int pr = blockIdx.x * 4 + sub;
    int row = pr + hi * NPAIR;
    __shared__ unsigned shn[2][4][32][2];
    float2 se;
    float4 sd;
    csr_row_l2(row, lane, se, sd);
    unsigned myx[2], myy[2];
    if (!hi) {
        unsigned base = (unsigned)pr * 64u + (unsigned)(lane * 2);
#pragma unroll
        for (int vv = 0; vv < 2; vv++) {
            unsigned k0 = vv ? f20 : f10, k1 = vv ? f21 : f11;
            unsigned a0, a1, b0, b1;
            tf2x32(k0, k1, base, base + HALFC, a0, a1);
            tf2x32(k0, k1, base + 1u, base + 1u + HALFC, b0, b1);
            myx[vv] = a0; myy[vv] = b0;
            shn[vv][sub][lane][0] = a1;
            shn[vv][sub][lane][1] = b1;
        }
    }
    __syncthreads();
    if (hi) {
#pragma unroll
        for (int vv = 0; vv < 2; vv++) {
            myx[vv] = shn[vv][sub][lane][0];
            myy[vv] = shn[vv][sub][lane][1];
        }
    }
    ((float2*)(g_e2 + (row << 6)))[lane] = se;
    // pre-noise view values: y2pre = se + sd(view parts); noise sign from y2pre
    float y1x = se.x + sd.x, y1y = se.y + sd.y;   // view 1
    float y2x = se.x + sd.z, y2y = se.y + sd.w;   // view 2
    {
        float nx = u32_to_unit(myx[0]), ny = u32_to_unit(myy[0]);
        float sc = EPSC * rsqrtf(wredsum(nx * nx + ny * ny));
        sd.x += sgn(y1x) * nx * sc;
        sd.y += sgn(y1y) * ny * sc;
    }
    {
        float nx = u32_to_unit(myx[1]), ny = u32_to_unit(myy[1]);
        float sc = EPSC * rsqrtf(wredsum(nx * nx + ny * ny));
        sd.z += sgn(y2x) * nx * sc;
        sd.w += sgn(y2y) * ny * sc;
    }
    g_d2[(row << 5) + lane] = pack4h(sd.x, sd.y, sd.z, sd.w);
}

// ---------------- BPR: warp per batch entry, layer-3 rows on the fly ----------------
__global__ void __launch_bounds__(256) k_bpr(const int* __restrict__ ul,
                                             const int* __restrict__ pl,
                                             const int* __restrict__ nl) {
    int w = (blockIdx.x * blockDim.x + threadIdx.x) >> 5;
    int lane = threadIdx.x & 31;
    if (w >= BATCHC) return;
    const float third = 1.f / 3.f;
    int ru = ul[w];
    int rp = N_USERS + pl[w];
    int rn = N_USERS + nl[w];
    float2 u3 = csr_row(g_e2, ru, lane);
    float2 p3 = csr_row(g_e2, rp, lane);
    float2 n3 = csr_row(g_e2, rn, lane);
    float2 u1 = ((const float2*)(g_e1 + (ru << 6)))[lane];
    float2 u2 = ((const float2*)(g_e2 + (ru << 6)))[lane];
    float2 p1 = ((const float2*)(g_e1 + (rp << 6)))[lane];
    float2 p2 = ((const float2*)(g_e2 + (rp << 6)))[lane];
    float2 n1 = ((const float2*)(g_e1 + (rn << 6)))[lane];
    float2 n2 = ((const float2*)(g_e2 + (rn << 6)))[lane];
    float ux = (u1.x + u2.x + u3.x) * third, uy = (u1.y + u2.y + u3.y) * third;
    float px = (p1.x + p2.x + p3.x) * third, py = (p1.y + p2.y + p3.y) * third;
    float nx = (n1.x + n2.x + n3.x) * third, ny = (n1.y + n2.y + n3.y) * third;
    float pos = wredsum(ux * px + uy * py);
    float neg = wredsum(ux * nx + uy * ny);
    float ssu = wredsum(ux * ux + uy * uy);
    float ssp = wredsum(px * px + py * py);
    if (lane == 0) {
        float d = pos - neg;
        float sig = 1.f / (1.f + expf(-d));
        atomicAdd(&g_acc[0], -logf(1e-7f + sig));
        atomicAdd(&g_acc[1], ssu);
        atomicAdd(&g_acc[2], ssp);
    }
}

// ---------------- order-free unique (both lists in one launch) ----------------
__global__ void k_unique2(const int* __restrict__ ul, const int* __restrict__ pl) {
    int i = blockIdx.x * blockDim.x + threadIdx.x;
    if (i >= 2 * BATCHC) return;
    int which = (i >= BATCHC);
    int j = which ? i - BATCHC : i;
    int v = which ? pl[j] : ul[j];
    int fidx = which ? (N_USERS + v) : v;
    if (atomicExch(&g_flags[fidx], 1) == 0) {
        int p = atomicAdd(which ? &g_icnt : &g_ucnt, 1);
        (which ? g_iidx : g_uidx)[p] = v;
    }
}

// ---------------- finalize both views: layer-3 + noise + normalize + pos ----------------
__global__ void __launch_bounds__(256) k_vfinal(unsigned f10, unsigned f11,
                                                unsigned f20, unsigned f21) {
    int w = (blockIdx.x * blockDim.x + threadIdx.x) >> 5;
    int lane = threadIdx.x & 31;
    if (w >= 2 * BATCHC) return;
    int isItem = (w >= BATCHC);
    int j = isItem ? w - BATCHC : w;
    int cnt = isItem ? g_icnt : g_ucnt;
    if (j >= cnt) return;
    int row = isItem ? (N_USERS + g_iidx[j]) : g_uidx[j];
    float4 a3 = csr_row_l3(row, lane);
    float nx, ny, sc;
    row_noise(row, lane, f10, f11, nx, ny, sc);
    a3.x += sgn(a3.x) * nx * sc;
    a3.y += sgn(a3.y) * ny * sc;
    row_noise(row, lane, f20, f21, nx, ny, sc);
    a3.z += sgn(a3.z) * nx * sc;
    a3.w += sgn(a3.w) * ny * sc;
    // reconstruct y1, y2 from e + delta
    float2 e1r = ((const float2*)(g_e1 + (row << 6)))[lane];
    float2 e2r = ((const float2*)(g_e2 + (row << 6)))[lane];
    float4 d1r = unpack4h(g_d1[(row << 5) + lane]);
    float4 d2r = unpack4h(g_d2[(row << 5) + lane]);
    float s1x = (e1r.x + d1r.x) + (e2r.x + d2r.x) + a3.x;
    float s1y = (e1r.y + d1r.y) + (e2r.y + d2r.y) + a3.y;
    float inv1 = rsqrtf(wredsum(s1x * s1x + s1y * s1y));
    s1x *= inv1; s1y *= inv1;
    float s2x = (e1r.x + d1r.z) + (e2r.x + d2r.z) + a3.z;
    float s2y = (e1r.y + d1r.w) + (e2r.y + d2r.w) + a3.w;
    float inv2 = rsqrtf(wredsum(s2x * s2x + s2y * s2y));
    s2x *= inv2; s2y *= inv2;
    float* d1 = isItem ? g_V1i : g_V1u;
    float* d2 = isItem ? g_V2i : g_V2u;
    ((float2*)(d1 + (j << 6)))[lane] = make_float2(s1x, s1y);
    ((float2*)(d2 + (j << 6)))[lane] = make_float2(s2x, s2y);
    float d = wredsum(s2x * s1x + s2y * s1y);
    if (lane == 0) (isItem ? g_posI : g_posU)[j] = d * INV_TEMP;
}

// ---------------- InfoNCE: 64x64 tile, 8x8 dots/thread, FMA exp ----------------
#define NCE_TILE 64
__global__ void __launch_bounds__(64) k_nce() {
    int which = blockIdx.z;
    const float* __restrict__ V1 = which ? g_V1i : g_V1u;
    const float* __restrict__ V2 = which ? g_V2i : g_V2u;
    float* __restrict__ S = g_S + which * BATCHC;
    int U = which ? g_icnt : g_ucnt;
    int rb = blockIdx.y * NCE_TILE;
    int cb = blockIdx.x * NCE_TILE;
    if (rb >= U || cb >= U) return;
    __shared__ float sh1[NCE_TILE][DIM + 1];
    __shared__ float sh2[NCE_TILE][DIM + 1];
    __shared__ float srow[NCE_TILE];
    int tid = threadIdx.x;
    for (int idx = tid; idx < NCE_TILE * 16; idx += 64) {
        int r = idx >> 4, q = idx & 15;
        float4 v = make_float4(0.f, 0.f, 0.f, 0.f);
        if (rb + r < U) v = ((const float4*)(V1 + ((rb + r) << 6)))[q];
        sh1[r][q * 4 + 0] = v.x; sh1[r][q * 4 + 1] = v.y;
        sh1[r][q * 4 + 2] = v.z; sh1[r][q * 4 + 3] = v.w;
        float4 w = make_float4(0.f, 0.f, 0.f, 0.f);
        if (cb + r < U) w = ((const float4*)(V2 + ((cb + r) << 6)))[q];
        sh2[r][q * 4 + 0] = w.x; sh2[r][q * 4 + 1] = w.y;
        sh2[r][q * 4 + 2] = w.z; sh2[r][q * 4 + 3] = w.w;
    }
    srow[tid] = 0.f;   // 64 threads == NCE_TILE
    __syncthreads();
    int tx = tid & 7, ty = tid >> 3;
    float acc[8][8];
#pragma unroll
    for (int i = 0; i < 8; i++)
#pragma unroll
        for (int j = 0; j < 8; j++) acc[i][j] = 0.f;
    for (int k = 0; k < DIM; k++) {
        float a[8], b[8];
#pragma unroll
        for (int i = 0; i < 8; i++) a[i] = sh1[ty * 8 + i][k];
#pragma unroll
        for (int j = 0; j < 8; j++) b[j] = sh2[tx * 8 + j][k];
#pragma unroll
        for (int i = 0; i < 8; i++)
#pragma unroll
            for (int j = 0; j < 8; j++) acc[i][j] = fmaf(a[i], b[j], acc[i][j]);
    }
#pragma unroll
    for (int i = 0; i < 8; i++) {
        int r = rb + ty * 8 + i;
        if (r >= U) continue;
        float s = 0.f;
#pragma unroll
        for (int j = 0; j < 8; j++) {
            int c = cb + tx * 8 + j;
            if (c < U) s += fexp(fmaf(acc[i][j], INV_TEMP, -5.0f));
        }
        atomicAdd(&srow[ty * 8 + i], s);
    }
    __syncthreads();
    if (rb + tid < U) atomicAdd(&S[rb + tid], srow[tid]);
}

__global__ void __launch_bounds__(256) k_ncefin() {
    int i = blockIdx.x * blockDim.x + threadIdx.x;
    int which = (i >= BATCHC);
    int j = i - which * BATCHC;
    int U = which ? g_icnt : g_ucnt;
    float c = 0.f;
    if (i < 2 * BATCHC && j < U)
        c = 5.0f + logf(g_S[i]) - (which ? g_posI[j] : g_posU[j]);
    c = wredsum(c);
    if ((threadIdx.x & 31) == 0 && c != 0.f)
        atomicAdd(&g_acc[3 + which], c);
}

__global__ void k_final(float* out) {
    if (threadIdx.x == 0) {
        float rec = g_acc[0] / (float)BATCHC;
        float reg = 1e-4f * (sqrtf(g_acc[1]) + sqrtf(g_acc[2]));
        float cl = 0.2f * (g_acc[3] / (float)g_ucnt + g_acc[4] / (float)g_icnt);
        out[0] = rec + reg + cl;
        out[1] = cl;
    }
}

// ---------------- launch ----------------
extern "C" void kernel_launch(void* const* d_in, const int* in_sizes, int n_in,
                              void* d_out, int out_size) {
    const float* ue = (const float*)d_in[0];
    const float* ie = (const float*)d_in[1];
    const float* av = (const float*)d_in[2];
    const int*   ar = (const int*)d_in[3];
    const int*   ac = (const int*)d_in[4];
    const int*   ul = (const int*)d_in[5];
    const int*   pl = (const int*)d_in[6];
    const int*   nl = (const int*)d_in[7];
    float* out = (float*)d_out;

    const int SCAN_BLOCKS = (N_NODESC + 1023) / 1024;
    const int PAIRED_BLOCKS = NPAIR / 4;   // 18750: 4 row-pairs per 8-warp block

    unsigned seeds[2] = {101u, 202u};
    unsigned fk[2][3][2];
    for (int vv = 0; vv < 2; vv++)
        for (int k = 0; k < 3; k++)
            tf2x32(0u, seeds[vv], 0u, (unsigned)k, fk[vv][k][0], fk[vv][k][1]);

    k_init<<<(N_NODESC + 255) / 256, 256>>>();
    k_hist<<<(NNZC + 255) / 256, 256>>>(ar);
    k_scan1<<<SCAN_BLOCKS, 1024>>>();
    k_scan2<<<1, 256>>>(SCAN_BLOCKS);
    k_scan3<<<SCAN_BLOCKS, 1024>>>();
    k_fill<<<(NNZC + 255) / 256, 256>>>(ar, ac, av);
    k_unique2<<<(2 * BATCHC + 255) / 256, 256>>>(ul, pl);

    // layer 1: e1 + fp16 noise deltas (paired tf)
    k_spmm_e1_noise<<<PAIRED_BLOCKS, 256>>>(ue, ie,
        fk[0][0][0], fk[0][0][1], fk[1][0][0], fk[1][0][1]);
    // layer 2: e2 = A*e1 and d2 = A*d1 + noise2, L2-resident gathers
    k_spmm_l2<<<PAIRED_BLOCKS, 256>>>(fk[0][1][0], fk[0][1][1], fk[1][1][0], fk[1][1][1]);
    k_bpr<<<(BATCHC * 32) / 256, 256>>>(ul, pl, nl);
    k_vfinal<<<(2 * BATCHC * 32) / 256, 256>>>(fk[0][2][0], fk[0][2][1], fk[1][2][0], fk[1][2][1]);

    dim3 nce_grid(BATCHC / NCE_TILE, BATCHC / NCE_TILE, 2);   // (64, 64, 2)
    k_nce<<<nce_grid, 64>>>();
    k_ncefin<<<(2 * BATCHC + 255) / 256, 256>>>();
    k_final<<<1, 32>>>(out);
}

// round 13
// speedup vs baseline: 1.1749x; 1.1749x over previous
#include <cuda_runtime.h>
#include <cuda_fp16.h>
#include <cstdint>

#define N_USERS 100000
#define N_ITEMS 50000
#define N_NODESC 150000
#define NNZC 2400000
#define DIM 64
#define BATCHC 4096
#define HALFC 4800000u
#define NPAIR 75000
#define EPSC 0.1f
#define INV_TEMP 5.0f

// ---------------- static device scratch (allocation-free) ----------------
__device__ float  g_e1 [N_NODESC * DIM];
__device__ float  g_e2 [N_NODESC * DIM];
__device__ uint2  g_d1 [N_NODESC * 32];   // half4 noise offsets (v1x,v1y,v2x,v2y) at [row*32+lane]
__device__ uint2  g_d2 [N_NODESC * 32];   // layer-2 view delta = A*d1 + noise2 offsets
__device__ int2   g_cv[NNZC];
__device__ int    g_rowptr[N_NODESC + 1];
__device__ int    g_cursor[N_NODESC];
__device__ int    g_counts[N_NODESC];
__device__ int    g_blocksums[256];
__device__ int    g_flags[N_NODESC];
__device__ int    g_uidx[BATCHC];
__device__ int    g_iidx[BATCHC];
__device__ int    g_ucnt;
__device__ int    g_icnt;
__device__ unsigned g_Vh[4][BATCHC * 32]; // half2-packed normalized views: [(view-1)*2+isItem][j*32+lane]
__device__ float  g_posU[BATCHC], g_posI[BATCHC];
__device__ float  g_S[2 * BATCHC];
__device__ float  g_acc[8];               // 0 rec, 1 ssu, 2 ssp, 3 nceU, 4 nceI

// ---------------- half pack/unpack ----------------
__device__ __forceinline__ uint2 pack4h(float a, float b, float c, float d) {
    __half2 lo = __floats2half2_rn(a, b);
    __half2 hi = __floats2half2_rn(c, d);
    uint2 r;
    r.x = *(const unsigned*)&lo;
    r.y = *(const unsigned*)&hi;
    return r;
}
__device__ __forceinline__ float4 unpack4h(uint2 u) {
    float2 lo = __half22float2(*(const __half2*)&u.x);
    float2 hi = __half22float2(*(const __half2*)&u.y);
    return make_float4(lo.x, lo.y, hi.x, hi.y);
}
__device__ __forceinline__ unsigned pack2h(float a, float b) {
    __half2 h = __floats2half2_rn(a, b);
    return *(const unsigned*)&h;
}

// ---------------- threefry-2x32 (exact JAX schedule) ----------------
__host__ __device__ __forceinline__ unsigned rl32(unsigned x, int r) {
    return (x << r) | (x >> (32 - r));
}
__host__ __device__ __forceinline__ void tf2x32(unsigned k0, unsigned k1,
                                                unsigned x0, unsigned x1,
                                                unsigned& o0, unsigned& o1) {
    unsigned k2 = k0 ^ k1 ^ 0x1BD11BDAu;
    x0 += k0; x1 += k1;
#define TFR(r) { x0 += x1; x1 = rl32(x1, r); x1 ^= x0; }
    TFR(13) TFR(15) TFR(26) TFR(6)
    x0 += k1; x1 += k2 + 1u;
    TFR(17) TFR(29) TFR(16) TFR(24)
    x0 += k2; x1 += k0 + 2u;
    TFR(13) TFR(15) TFR(26) TFR(6)
    x0 += k0; x1 += k1 + 3u;
    TFR(17) TFR(29) TFR(16) TFR(24)
    x0 += k1; x1 += k2 + 4u;
    TFR(13) TFR(15) TFR(26) TFR(6)
    x0 += k2; x1 += k0 + 5u;
#undef TFR
    o0 = x0; o1 = x1;
}
__device__ __forceinline__ float u32_to_unit(unsigned b) {
    return __uint_as_float((b >> 9) | 0x3f800000u) - 1.0f;
}
__device__ __forceinline__ float wredsum(float v) {
#pragma unroll
    for (int o = 16; o; o >>= 1) v += __shfl_xor_sync(0xffffffffu, v, o);
    return v;
}
__device__ __forceinline__ float sgn(float x) {
    return (x > 0.f) ? 1.f : ((x < 0.f) ? -1.f : 0.f);
}
// FMA-only exp for x in [-15, 0]: 2^(x*log2e) with degree-6 Taylor of 2^f
__device__ __forceinline__ float fexp(float x) {
    float t = x * 1.4426950408889634f;
    float fi = floorf(t);
    float f = t - fi;
    float p = 1.5404e-4f;
    p = fmaf(p, f, 1.3333558e-3f);
    p = fmaf(p, f, 9.6181291e-3f);
    p = fmaf(p, f, 5.5504109e-2f);
    p = fmaf(p, f, 2.4022651e-1f);
    p = fmaf(p, f, 6.9314718e-1f);
    p = fmaf(p, f, 1.0f);
    return __int_as_float(((int)fi + 127) << 23) * p;
}

// per-row noise for standalone rows (vfinal only, ~8K rows)
__device__ __forceinline__ void row_noise(int row, int lane, unsigned k0, unsigned k1,
                                          float& nx, float& ny, float& sc) {
    int half = (row >= NPAIR);
    unsigned base = (unsigned)(half ? row - NPAIR : row) * 64u + (unsigned)(lane * 2);
    unsigned a0, a1, b0, b1;
    tf2x32(k0, k1, base, base + HALFC, a0, a1);
    tf2x32(k0, k1, base + 1u, base + 1u + HALFC, b0, b1);
    nx = u32_to_unit(half ? a1 : a0);
    ny = u32_to_unit(half ? b1 : b0);
    sc = EPSC * rsqrtf(wredsum(nx * nx + ny * ny));
}

// warp computes one CSR row (float2 source); 4-wide MLP
__device__ __forceinline__ float2 csr_row(const float* __restrict__ x, int row, int lane) {
    int s = g_rowptr[row], e = g_rowptr[row + 1];
    float ax = 0.f, ay = 0.f, bx = 0.f, by = 0.f;
    float cx = 0.f, cy = 0.f, dx = 0.f, dy = 0.f;
    int i = s;
    for (; i + 3 < e; i += 4) {
        int2 c0 = g_cv[i], c1 = g_cv[i + 1], c2 = g_cv[i + 2], c3 = g_cv[i + 3];
        float2 p0 = ((const float2*)(x + (c0.x << 6)))[lane];
        float2 p1 = ((const float2*)(x + (c1.x << 6)))[lane];
        float2 p2 = ((const float2*)(x + (c2.x << 6)))[lane];
        float2 p3 = ((const float2*)(x + (c3.x << 6)))[lane];
        float v0 = __int_as_float(c0.y), v1 = __int_as_float(c1.y);
        float v2 = __int_as_float(c2.y), v3 = __int_as_float(c3.y);
        ax = fmaf(v0, p0.x, ax); ay = fmaf(v0, p0.y, ay);
        bx = fmaf(v1, p1.x, bx); by = fmaf(v1, p1.y, by);
        cx = fmaf(v2, p2.x, cx); cy = fmaf(v2, p2.y, cy);
        dx = fmaf(v3, p3.x, dx); dy = fmaf(v3, p3.y, dy);
    }
    for (; i < e; i++) {
        int2 c0 = g_cv[i];
        float2 p0 = ((const float2*)(x + (c0.x << 6)))[lane];
        float v0 = __int_as_float(c0.y);
        ax = fmaf(v0, p0.x, ax); ay = fmaf(v0, p0.y, ay);
    }
    return make_float2((ax + bx) + (cx + dx), (ay + by) + (cy + dy));
}

// layer-1 gather directly from the two input embedding arrays
__device__ __forceinline__ float2 csr_row_in(const float* __restrict__ ue,
                                             const float* __restrict__ ie,
                                             int row, int lane) {
    int s = g_rowptr[row], e = g_rowptr[row + 1];
    float ax = 0.f, ay = 0.f, bx = 0.f, by = 0.f;
    float cx = 0.f, cy = 0.f, dx = 0.f, dy = 0.f;
    int i = s;
#define SRC(c) ((c) < N_USERS ? ue + ((c) << 6) : ie + (((c) - N_USERS) << 6))
    for (; i + 3 < e; i += 4) {
        int2 c0 = g_cv[i], c1 = g_cv[i + 1], c2 = g_cv[i + 2], c3 = g_cv[i + 3];
        float2 p0 = ((const float2*)SRC(c0.x))[lane];
        float2 p1 = ((const float2*)SRC(c1.x))[lane];
        float2 p2 = ((const float2*)SRC(c2.x))[lane];
        float2 p3 = ((const float2*)SRC(c3.x))[lane];
        float v0 = __int_as_float(c0.y), v1 = __int_as_float(c1.y);
        float v2 = __int_as_float(c2.y), v3 = __int_as_float(c3.y);
        ax = fmaf(v0, p0.x, ax); ay = fmaf(v0, p0.y, ay);
        bx = fmaf(v1, p1.x, bx); by = fmaf(v1, p1.y, by);
        cx = fmaf(v2, p2.x, cx); cy = fmaf(v2, p2.y, cy);
        dx = fmaf(v3, p3.x, dx); dy = fmaf(v3, p3.y, dy);
    }
    for (; i < e; i++) {
        int2 c0 = g_cv[i];
        float2 p0 = ((const float2*)SRC(c0.x))[lane];
        float v0 = __int_as_float(c0.y);
        ax = fmaf(v0, p0.x, ax); ay = fmaf(v0, p0.y, ay);
    }
#undef SRC
    return make_float2((ax + bx) + (cx + dx), (ay + by) + (cy + dy));
}

// one CSR pass over e1 (float2) + d1 (half4): se = A*e1, sd = A*d1
__device__ __forceinline__ void csr_row_l2(int row, int lane, float2& se, float4& sd) {
    int s = g_rowptr[row], e = g_rowptr[row + 1];
    float ex0 = 0.f, ey0 = 0.f, ex1 = 0.f, ey1 = 0.f;
    float dx0 = 0.f, dy0 = 0.f, dz0 = 0.f, dw0 = 0.f;
    float dx1 = 0.f, dy1 = 0.f, dz1 = 0.f, dw1 = 0.f;
    int i = s;
    for (; i + 3 < e; i += 4) {
        int2 c0 = g_cv[i], c1 = g_cv[i + 1], c2 = g_cv[i + 2], c3 = g_cv[i + 3];
        float2 q0 = ((const float2*)(g_e1 + (c0.x << 6)))[lane];
        float2 q1 = ((const float2*)(g_e1 + (c1.x << 6)))[lane];
        float2 q2 = ((const float2*)(g_e1 + (c2.x << 6)))[lane];
        float2 q3 = ((const float2*)(g_e1 + (c3.x << 6)))[lane];
        uint2 u0 = g_d1[(c0.x << 5) + lane];
        uint2 u1 = g_d1[(c1.x << 5) + lane];
        uint2 u2 = g_d1[(c2.x << 5) + lane];
        uint2 u3 = g_d1[(c3.x << 5) + lane];
        float v0 = __int_as_float(c0.y), v1 = __int_as_float(c1.y);
        float v2 = __int_as_float(c2.y), v3 = __int_as_float(c3.y);
        float4 p0 = unpack4h(u0), p1 = unpack4h(u1), p2 = unpack4h(u2), p3 = unpack4h(u3);
        ex0 = fmaf(v0, q0.x, ex0); ey0 = fmaf(v0, q0.y, ey0);
        ex1 = fmaf(v1, q1.x, ex1); ey1 = fmaf(v1, q1.y, ey1);
        ex0 = fmaf(v2, q2.x, ex0); ey0 = fmaf(v2, q2.y, ey0);
        ex1 = fmaf(v3, q3.x, ex1); ey1 = fmaf(v3, q3.y, ey1);
        dx0 = fmaf(v0, p0.x, dx0); dy0 = fmaf(v0, p0.y, dy0);
        dz0 = fmaf(v0, p0.z, dz0); dw0 = fmaf(v0, p0.w, dw0);
        dx1 = fmaf(v1, p1.x, dx1); dy1 = fmaf(v1, p1.y, dy1);
        dz1 = fmaf(v1, p1.z, dz1); dw1 = fmaf(v1, p1.w, dw1);
        dx0 = fmaf(v2, p2.x, dx0); dy0 = fmaf(v2, p2.y, dy0);
        dz0 = fmaf(v2, p2.z, dz0); dw0 = fmaf(v2, p2.w, dw0);
        dx1 = fmaf(v3, p3.x, dx1); dy1 = fmaf(v3, p3.y, dy1);
        dz1 = fmaf(v3, p3.z, dz1); dw1 = fmaf(v3, p3.w, dw1);
    }
    for (; i < e; i++) {
        int2 c0 = g_cv[i];
        float2 q0 = ((const float2*)(g_e1 + (c0.x << 6)))[lane];
        float4 p0 = unpack4h(g_d1[(c0.x << 5) + lane]);
        float v0 = __int_as_float(c0.y);
        ex0 = fmaf(v0, q0.x, ex0); ey0 = fmaf(v0, q0.y, ey0);
        dx0 = fmaf(v0, p0.x, dx0); dy0 = fmaf(v0, p0.y, dy0);
        dz0 = fmaf(v0, p0.z, dz0); dw0 = fmaf(v0, p0.w, dw0);
    }
    se = make_float2(ex0 + ex1, ey0 + ey1);
    sd = make_float4(dx0 + dx1, dy0 + dy1, dz0 + dz1, dw0 + dw1);
}

// layer-3 view gather: A*(e2 + d2) for one row, both views
__device__ __forceinline__ float4 csr_row_l3(int row, int lane) {
    int s = g_rowptr[row], e = g_rowptr[row + 1];
    float ax = 0.f, ay = 0.f, az = 0.f, aw = 0.f;
    float bx = 0.f, by = 0.f, bz = 0.f, bw = 0.f;
    int i = s;
    for (; i + 1 < e; i += 2) {
        int2 c0 = g_cv[i], c1 = g_cv[i + 1];
        float2 q0 = ((const float2*)(g_e2 + (c0.x << 6)))[lane];
        float2 q1 = ((const float2*)(g_e2 + (c1.x << 6)))[lane];
        float4 p0 = unpack4h(g_d2[(c0.x << 5) + lane]);
        float4 p1 = unpack4h(g_d2[(c1.x << 5) + lane]);
        float v0 = __int_as_float(c0.y), v1 = __int_as_float(c1.y);
        ax = fmaf(v0, q0.x + p0.x, ax); ay = fmaf(v0, q0.y + p0.y, ay);
        az = fmaf(v0, q0.x + p0.z, az); aw = fmaf(v0, q0.y + p0.w, aw);
        bx = fmaf(v1, q1.x + p1.x, bx); by = fmaf(v1, q1.y + p1.y, by);
        bz = fmaf(v1, q1.x + p1.z, bz); bw = fmaf(v1, q1.y + p1.w, bw);
    }
    if (i < e) {
        int2 c0 = g_cv[i];
        float2 q0 = ((const float2*)(g_e2 + (c0.x << 6)))[lane];
        float4 p0 = unpack4h(g_d2[(c0.x << 5) + lane]);
        float v0 = __int_as_float(c0.y);
        ax = fmaf(v0, q0.x + p0.x, ax); ay = fmaf(v0, q0.y + p0.y, ay);
        az = fmaf(v0, q0.x + p0.z, az); aw = fmaf(v0, q0.y + p0.w, aw);
    }
    return make_float4(ax + bx, ay + by, az + bz, aw + bw);
}

// ---------------- setup ----------------
__global__ void k_init() {
    int i = blockIdx.x * blockDim.x + threadIdx.x;
    if (i < N_NODESC) { g_flags[i] = 0; g_counts[i] = 0; }
    if (i < 2 * BATCHC) g_S[i] = 0.f;
    if (i < 8) g_acc[i] = 0.f;
    if (i == 0) { g_ucnt = 0; g_icnt = 0; }
}
__global__ void k_hist(const int* __restrict__ rows) {
    int i = blockIdx.x * blockDim.x + threadIdx.x;
    if (i < NNZC) atomicAdd(&g_counts[rows[i]], 1);
}
__global__ void k_scan1() {
    __shared__ int sh[1024];
    int g = blockIdx.x * 1024 + threadIdx.x;
    int v = (g < N_NODESC) ? g_counts[g] : 0;
    sh[threadIdx.x] = v;
    __syncthreads();
    for (int off = 1; off < 1024; off <<= 1) {
        int t = (threadIdx.x >= off) ? sh[threadIdx.x - off] : 0;
        __syncthreads();
        sh[threadIdx.x] += t;
        __syncthreads();
    }
    if (g < N_NODESC) g_rowptr[g] = sh[threadIdx.x] - v;
    if (threadIdx.x == 1023) g_blocksums[blockIdx.x] = sh[1023];
}
__global__ void k_scan2(int nblocks) {
    __shared__ int sh[256];
    int t = threadIdx.x;
    int v = (t < nblocks) ? g_blocksums[t] : 0;
    sh[t] = v;
    __syncthreads();
    for (int off = 1; off < 256; off <<= 1) {
        int p = (t >= off) ? sh[t - off] : 0;
        __syncthreads();
        sh[t] += p;
        __syncthreads();
    }
    if (t < nblocks) g_blocksums[t] = sh[t] - v;   // exclusive
    if (t == nblocks - 1) g_rowptr[N_NODESC] = sh[t];
}
__global__ void k_scan3() {
    int g = blockIdx.x * blockDim.x + threadIdx.x;
    if (g < N_NODESC) {
        int v = g_rowptr[g] + g_blocksums[g >> 10];
        g_rowptr[g] = v;
        g_cursor[g] = v;
    }
}
__global__ void k_fill(const int* __restrict__ rows, const int* __restrict__ cols,
                       const float* __restrict__ vals) {
    int i = blockIdx.x * blockDim.x + threadIdx.x;
    if (i < NNZC) {
        int p = atomicAdd(&g_cursor[rows[i]], 1);
        g_cv[p] = make_int2(cols[i], __float_as_int(vals[i]));
    }
}

// ---------------- layer 1: e1 = A*[ue;ie]; d1 = fp16 noise offsets (paired tf) ----------------
__global__ void __launch_bounds__(256) k_spmm_e1_noise(const float* __restrict__ ue,
                                                       const float* __restrict__ ie,
                                                       unsigned f10, unsigned f11,
                                                       unsigned f20, unsigned f21) {
    int warp = threadIdx.x >> 5;
    int lane = threadIdx.x & 31;
    int sub = warp & 3;
    int hi = warp >> 2;
    int pr = blockIdx.x * 4 + sub;
    int row = pr + hi * NPAIR;
    __shared__ unsigned shn[2][4][32][2];
    float2 ea = csr_row_in(ue, ie, row, lane);
    unsigned myx[2], myy[2];
    if (!hi) {
        unsigned base = (unsigned)pr * 64u + (unsigned)(lane * 2);
#pragma unroll
        for (int vv = 0; vv < 2; vv++) {
            unsigned k0 = vv ? f20 : f10, k1 = vv ? f21 : f11;
            unsigned a0, a1, b0, b1;
            tf2x32(k0, k1, base, base + HALFC, a0, a1);
            tf2x32(k0, k1, base + 1u, base + 1u + HALFC, b0, b1);
            myx[vv] = a0; myy[vv] = b0;
            shn[vv][sub][lane][0] = a1;
            shn[vv][sub][lane][1] = b1;
        }
    }
    __syncthreads();
    if (hi) {
#pragma unroll
        for (int vv = 0; vv < 2; vv++) {
            myx[vv] = shn[vv][sub][lane][0];
            myy[vv] = shn[vv][sub][lane][1];
        }
    }
    ((float2*)(g_e1 + (row << 6)))[lane] = ea;
    float o1x, o1y, o2x, o2y;
    {
        float nx = u32_to_unit(myx[0]), ny = u32_to_unit(myy[0]);
        float sc = EPSC * rsqrtf(wredsum(nx * nx + ny * ny));
        o1x = sgn(ea.x) * nx * sc;
        o1y = sgn(ea.y) * ny * sc;
    }
    {
        float nx = u32_to_unit(myx[1]), ny = u32_to_unit(myy[1]);
        float sc = EPSC * rsqrtf(wredsum(nx * nx + ny * ny));
        o2x = sgn(ea.x) * nx * sc;
        o2y = sgn(ea.y) * ny * sc;
    }
    g_d1[(row << 5) + lane] = pack4h(o1x, o1y, o2x, o2y);
}

// ---------------- layer 2: e2 = A*e1; d2 = A*d1 + noise2 offsets (paired tf) ----------------
__global__ void __launch_bounds__(256) k_spmm_l2(unsigned f10, unsigned f11,
                                                 unsigned f20, unsigned f21) {
    int warp = threadIdx.x >> 5;
    int lane = threadIdx.x & 31;
    int sub = warp & 3;
    int hi = warp >> 2;
    int pr = blockIdx.x * 4 + sub;
    int row = pr + hi * NPAIR;
    __shared__ unsigned shn[2][4][32][2];
    float2 se;
    float4 sd;
    csr_row_l2(row, lane, se, sd);
    unsigned myx[2], myy[2];
    if (!hi) {
        unsigned base = (unsigned)pr * 64u + (unsigned)(lane * 2);
#pragma unroll
        for (int vv = 0; vv < 2; vv++) {
            unsigned k0 = vv ? f20 : f10, k1 = vv ? f21 : f11;
            unsigned a0, a1, b0, b1;
            tf2x32(k0, k1, base, base + HALFC, a0, a1);
            tf2x32(k0, k1, base + 1u, base + 1u + HALFC, b0, b1);
            myx[vv] = a0; myy[vv] = b0;
            shn[vv][sub][lane][0] = a1;
            shn[vv][sub][lane][1] = b1;
        }
    }
    __syncthreads();
    if (hi) {
#pragma unroll
        for (int vv = 0; vv < 2; vv++) {
            myx[vv] = shn[vv][sub][lane][0];
            myy[vv] = shn[vv][sub][lane][1];
        }
    }
    ((float2*)(g_e2 + (row << 6)))[lane] = se;
    // pre-noise view values: y2pre = se + sd(view parts); noise sign from y2pre
    float y1x = se.x + sd.x, y1y = se.y + sd.y;   // view 1
    float y2x = se.x + sd.z, y2y = se.y + sd.w;   // view 2
    {
        float nx = u32_to_unit(myx[0]), ny = u32_to_unit(myy[0]);
        float sc = EPSC * rsqrtf(wredsum(nx * nx + ny * ny));
        sd.x += sgn(y1x) * nx * sc;
        sd.y += sgn(y1y) * ny * sc;
    }
    {
        float nx = u32_to_unit(myx[1]), ny = u32_to_unit(myy[1]);
        float sc = EPSC * rsqrtf(wredsum(nx * nx + ny * ny));
        sd.z += sgn(y2x) * nx * sc;
        sd.w += sgn(y2y) * ny * sc;
    }
    g_d2[(row << 5) + lane] = pack4h(sd.x, sd.y, sd.z, sd.w);
}

// ---------------- BPR: warp per batch entry, layer-3 rows on the fly ----------------
__global__ void __launch_bounds__(256) k_bpr(const int* __restrict__ ul,
                                             const int* __restrict__ pl,
                                             const int* __restrict__ nl) {
    int w = (blockIdx.x * blockDim.x + threadIdx.x) >> 5;
    int lane = threadIdx.x & 31;
    if (w >= BATCHC) return;
    const float third = 1.f / 3.f;
    int ru = ul[w];
    int rp = N_USERS + pl[w];
    int rn = N_USERS + nl[w];
    float2 u3 = csr_row(g_e2, ru, lane);
    float2 p3 = csr_row(g_e2, rp, lane);
    float2 n3 = csr_row(g_e2, rn, lane);
    float2 u1 = ((const float2*)(g_e1 + (ru << 6)))[lane];
    float2 u2 = ((const float2*)(g_e2 + (ru << 6)))[lane];
    float2 p1 = ((const float2*)(g_e1 + (rp << 6)))[lane];
    float2 p2 = ((const float2*)(g_e2 + (rp << 6)))[lane];
    float2 n1 = ((const float2*)(g_e1 + (rn << 6)))[lane];
    float2 n2 = ((const float2*)(g_e2 + (rn << 6)))[lane];
    float ux = (u1.x + u2.x + u3.x) * third, uy = (u1.y + u2.y + u3.y) * third;
    float px = (p1.x + p2.x + p3.x) * third, py = (p1.y + p2.y + p3.y) * third;
    float nx = (n1.x + n2.x + n3.x) * third, ny = (n1.y + n2.y + n3.y) * third;
    float pos = wredsum(ux * px + uy * py);
    float neg = wredsum(ux * nx + uy * ny);
    float ssu = wredsum(ux * ux + uy * uy);
    float ssp = wredsum(px * px + py * py);
    if (lane == 0) {
        float d = pos - neg;
        float sig = 1.f / (1.f + expf(-d));
        atomicAdd(&g_acc[0], -logf(1e-7f + sig));
        atomicAdd(&g_acc[1], ssu);
        atomicAdd(&g_acc[2], ssp);
    }
}

// ---------------- order-free unique (both lists in one launch) ----------------
__global__ void k_unique2(const int* __restrict__ ul, const int* __restrict__ pl) {
    int i = blockIdx.x * blockDim.x + threadIdx.x;
    if (i >= 2 * BATCHC) return;
    int which = (i >= BATCHC);
    int j = which ? i - BATCHC : i;
    int v = which ? pl[j] : ul[j];
    int fidx = which ? (N_USERS + v) : v;
    if (atomicExch(&g_flags[fidx], 1) == 0) {
        int p = atomicAdd(which ? &g_icnt : &g_ucnt, 1);
        (which ? g_iidx : g_uidx)[p] = v;
    }
}

// ---------------- finalize both views: layer-3 + noise + normalize + pos ----------------
__global__ void __launch_bounds__(256) k_vfinal(unsigned f10, unsigned f11,
                                                unsigned f20, unsigned f21) {
    int w = (blockIdx.x * blockDim.x + threadIdx.x) >> 5;
    int lane = threadIdx.x & 31;
    if (w >= 2 * BATCHC) return;
    int isItem = (w >= BATCHC);
    int j = isItem ? w - BATCHC : w;
    int cnt = isItem ? g_icnt : g_ucnt;
    if (j >= cnt) return;
    int row = isItem ? (N_USERS + g_iidx[j]) : g_uidx[j];
    float4 a3 = csr_row_l3(row, lane);
    float nx, ny, sc;
    row_noise(row, lane, f10, f11, nx, ny, sc);
    a3.x += sgn(a3.x) * nx * sc;
    a3.y += sgn(a3.y) * ny * sc;
    row_noise(row, lane, f20, f21, nx, ny, sc);
    a3.z += sgn(a3.z) * nx * sc;
    a3.w += sgn(a3.w) * ny * sc;
    // reconstruct y1, y2 from e + delta
    float2 e1r = ((const float2*)(g_e1 + (row << 6)))[lane];
    float2 e2r = ((const float2*)(g_e2 + (row << 6)))[lane];
    float4 d1r = unpack4h(g_d1[(row << 5) + lane]);
    float4 d2r = unpack4h(g_d2[(row << 5) + lane]);
    float s1x = (e1r.x + d1r.x) + (e2r.x + d2r.x) + a3.x;
    float s1y = (e1r.y + d1r.y) + (e2r.y + d2r.y) + a3.y;
    float inv1 = rsqrtf(wredsum(s1x * s1x + s1y * s1y));
    s1x *= inv1; s1y *= inv1;
    float s2x = (e1r.x + d1r.z) + (e2r.x + d2r.z) + a3.z;
    float s2y = (e1r.y + d1r.w) + (e2r.y + d2r.w) + a3.w;
    float inv2 = rsqrtf(wredsum(s2x * s2x + s2y * s2y));
    s2x *= inv2; s2y *= inv2;
    g_Vh[0 * 2 + isItem][(j << 5) + lane] = pack2h(s1x, s1y);
    g_Vh[1 * 2 + isItem][(j << 5) + lane] = pack2h(s2x, s2y);
    float d = wredsum(s2x * s1x + s2y * s1y);
    if (lane == 0) (isItem ? g_posI : g_posU)[j] = d * INV_TEMP;
}

// ---------------- InfoNCE: 64x64 tile, 8x8 dots/thread, half2 HFMA2 + FMA exp ----------------
#define NCE_TILE 64
__global__ void __launch_bounds__(64) k_nce() {
    int which = blockIdx.z;
    const unsigned* __restrict__ V1 = g_Vh[0 * 2 + which];
    const unsigned* __restrict__ V2 = g_Vh[1 * 2 + which];
    float* __restrict__ S = g_S + which * BATCHC;
    int U = which ? g_icnt : g_ucnt;
    int rb = blockIdx.y * NCE_TILE;
    int cb = blockIdx.x * NCE_TILE;
    if (rb >= U || cb >= U) return;
    __shared__ __half2 sh1[NCE_TILE][33];
    __shared__ __half2 sh2[NCE_TILE][33];
    __shared__ float srow[NCE_TILE];
    int tid = threadIdx.x;
    const __half2 hzero = __floats2half2_rn(0.f, 0.f);
    for (int idx = tid; idx < NCE_TILE * 32; idx += 64) {
        int r = idx >> 5, q = idx & 31;
        unsigned v = (rb + r < U) ? V1[((rb + r) << 5) + q] : 0u;
        unsigned w = (cb + r < U) ? V2[((cb + r) << 5) + q] : 0u;
        sh1[r][q] = *(const __half2*)&v;
        sh2[r][q] = *(const __half2*)&w;
    }
    srow[tid] = 0.f;   // 64 threads == NCE_TILE
    __syncthreads();
    int tx = tid & 7, ty = tid >> 3;
    __half2 acc[8][8];
#pragma unroll
    for (int i = 0; i < 8; i++)
#pragma unroll
        for (int j = 0; j < 8; j++) acc[i][j] = hzero;
    for (int k = 0; k < 32; k++) {
        __half2 a[8], b[8];
#pragma unroll
        for (int i = 0; i < 8; i++) a[i] = sh1[ty * 8 + i][k];
#pragma unroll
        for (int j = 0; j < 8; j++) b[j] = sh2[tx * 8 + j][k];
#pragma unroll
        for (int i = 0; i < 8; i++)
#pragma unroll
            for (int j = 0; j < 8; j++) acc[i][j] = __hfma2(a[i], b[j], acc[i][j]);
    }
#pragma unroll
    for (int i = 0; i < 8; i++) {
        int r = rb + ty * 8 + i;
        if (r >= U) continue;
        float s = 0.f;
#pragma unroll
        for (int j = 0; j < 8; j++) {
            int c = cb + tx * 8 + j;
            if (c < U) {
                float2 f = __half22float2(acc[i][j]);
                s += fexp(fmaf(f.x + f.y, INV_TEMP, -5.0f));
            }
        }
        atomicAdd(&srow[ty * 8 + i], s);
    }
    __syncthreads();
    if (rb + tid < U) atomicAdd(&S[rb + tid], srow[tid]);
}

__global__ void __launch_bounds__(256) k_ncefin() {
    int i = blockIdx.x * blockDim.x + threadIdx.x;
    int which = (i >= BATCHC);
    int j = i - which * BATCHC;
    int U = which ? g_icnt : g_ucnt;
    float c = 0.f;
    if (i < 2 * BATCHC && j < U)
        c = 5.0f + logf(g_S[i]) - (which ? g_posI[j] : g_posU[j]);
    c = wredsum(c);
    if ((threadIdx.x & 31) == 0 && c != 0.f)
        atomicAdd(&g_acc[3 + which], c);
}

__global__ void k_final(float* out) {
    if (threadIdx.x == 0) {
        float rec = g_acc[0] / (float)BATCHC;
        float reg = 1e-4f * (sqrtf(g_acc[1]) + sqrtf(g_acc[2]));
        float cl = 0.2f * (g_acc[3] / (float)g_ucnt + g_acc[4] / (float)g_icnt);
        out[0] = rec + reg + cl;
        out[1] = cl;
    }
}

// ---------------- launch ----------------
extern "C" void kernel_launch(void* const* d_in, const int* in_sizes, int n_in,
                              void* d_out, int out_size) {
    const float* ue = (const float*)d_in[0];
    const float* ie = (const float*)d_in[1];
    const float* av = (const float*)d_in[2];
    const int*   ar = (const int*)d_in[3];
    const int*   ac = (const int*)d_in[4];
    const int*   ul = (const int*)d_in[5];
    const int*   pl = (const int*)d_in[6];
    const int*   nl = (const int*)d_in[7];
    float* out = (float*)d_out;

    const int SCAN_BLOCKS = (N_NODESC + 1023) / 1024;
    const int PAIRED_BLOCKS = NPAIR / 4;   // 18750: 4 row-pairs per 8-warp block

    unsigned seeds[2] = {101u, 202u};
    unsigned fk[2][3][2];
    for (int vv = 0; vv < 2; vv++)
        for (int k = 0; k < 3; k++)
            tf2x32(0u, seeds[vv], 0u, (unsigned)k, fk[vv][k][0], fk[vv][k][1]);

    k_init<<<(N_NODESC + 255) / 256, 256>>>();
    k_hist<<<(NNZC + 255) / 256, 256>>>(ar);
    k_scan1<<<SCAN_BLOCKS, 1024>>>();
    k_scan2<<<1, 256>>>(SCAN_BLOCKS);
    k_scan3<<<SCAN_BLOCKS, 1024>>>();
    k_fill<<<(NNZC + 255) / 256, 256>>>(ar, ac, av);
    k_unique2<<<(2 * BATCHC + 255) / 256, 256>>>(ul, pl);

    // layer 1: e1 + fp16 noise deltas (paired tf)
    k_spmm_e1_noise<<<PAIRED_BLOCKS, 256>>>(ue, ie,
        fk[0][0][0], fk[0][0][1], fk[1][0][0], fk[1][0][1]);
    // layer 2: e2 = A*e1 and d2 = A*d1 + noise2, L2-resident gathers
    k_spmm_l2<<<PAIRED_BLOCKS, 256>>>(fk[0][1][0], fk[0][1][1], fk[1][1][0], fk[1][1][1]);
    k_bpr<<<(BATCHC * 32) / 256, 256>>>(ul, pl, nl);
    k_vfinal<<<(2 * BATCHC * 32) / 256, 256>>>(fk[0][2][0], fk[0][2][1], fk[1][2][0], fk[1][2][1]);

    dim3 nce_grid(BATCHC / NCE_TILE, BATCHC / NCE_TILE, 2);   // (64, 64, 2)
    k_nce<<<nce_grid, 64>>>();
    k_ncefin<<<(2 * BATCHC + 255) / 256, 256>>>();
    k_final<<<1, 32>>>(out);
}

// round 14
// speedup vs baseline: 1.2008x; 1.0220x over previous
#include <cuda_runtime.h>
#include <cuda_fp16.h>
#include <cstdint>

#define N_USERS 100000
#define N_ITEMS 50000
#define N_NODESC 150000
#define NNZC 2400000
#define DIM 64
#define BATCHC 4096
#define HALFC 4800000u
#define NPAIR 75000
#define EPSC 0.1f
#define INV_TEMP 5.0f

// ---------------- static device scratch (allocation-free) ----------------
__device__ float  g_e1 [N_NODESC * DIM];
__device__ float  g_e2 [N_NODESC * DIM];
__device__ uint2  g_d1 [N_NODESC * 32];   // half4 noise offsets (v1x,v1y,v2x,v2y) at [row*32+lane]
__device__ uint2  g_d2 [N_NODESC * 32];   // layer-2 view delta = A*d1 + noise2 offsets
__device__ int2   g_cv[NNZC];
__device__ int    g_rowptr[N_NODESC + 1];
__device__ int    g_cursor[N_NODESC];
__device__ int    g_counts[N_NODESC];
__device__ int    g_blocksums[256];
__device__ int    g_flags[N_NODESC];
__device__ int    g_uidx[BATCHC];
__device__ int    g_iidx[BATCHC];
__device__ int    g_ucnt;
__device__ int    g_icnt;
__device__ unsigned g_Vh[4][BATCHC * 32]; // half2-packed normalized views: [(view-1)*2+isItem][j*32+lane]
__device__ float  g_posU[BATCHC], g_posI[BATCHC];
__device__ float  g_S[2 * BATCHC];
__device__ float  g_acc[8];               // 0 rec, 1 ssu, 2 ssp, 3 nceU, 4 nceI

// ---------------- half pack/unpack ----------------
__device__ __forceinline__ uint2 pack4h(float a, float b, float c, float d) {
    __half2 lo = __floats2half2_rn(a, b);
    __half2 hi = __floats2half2_rn(c, d);
    uint2 r;
    r.x = *(const unsigned*)&lo;
    r.y = *(const unsigned*)&hi;
    return r;
}
__device__ __forceinline__ float4 unpack4h(uint2 u) {
    float2 lo = __half22float2(*(const __half2*)&u.x);
    float2 hi = __half22float2(*(const __half2*)&u.y);
    return make_float4(lo.x, lo.y, hi.x, hi.y);
}
__device__ __forceinline__ unsigned pack2h(float a, float b) {
    __half2 h = __floats2half2_rn(a, b);
    return *(const unsigned*)&h;
}

// ---------------- threefry-2x32 (exact JAX schedule) ----------------
__host__ __device__ __forceinline__ unsigned rl32(unsigned x, int r) {
    return (x << r) | (x >> (32 - r));
}
__host__ __device__ __forceinline__ void tf2x32(unsigned k0, unsigned k1,
                                                unsigned x0, unsigned x1,
                                                unsigned& o0, unsigned& o1) {
    unsigned k2 = k0 ^ k1 ^ 0x1BD11BDAu;
    x0 += k0; x1 += k1;
#define TFR(r) { x0 += x1; x1 = rl32(x1, r); x1 ^= x0; }
    TFR(13) TFR(15) TFR(26) TFR(6)
    x0 += k1; x1 += k2 + 1u;
    TFR(17) TFR(29) TFR(16) TFR(24)
    x0 += k2; x1 += k0 + 2u;
    TFR(13) TFR(15) TFR(26) TFR(6)
    x0 += k0; x1 += k1 + 3u;
    TFR(17) TFR(29) TFR(16) TFR(24)
    x0 += k1; x1 += k2 + 4u;
    TFR(13) TFR(15) TFR(26) TFR(6)
    x0 += k2; x1 += k0 + 5u;
#undef TFR
    o0 = x0; o1 = x1;
}
__device__ __forceinline__ float u32_to_unit(unsigned b) {
    return __uint_as_float((b >> 9) | 0x3f800000u) - 1.0f;
}
__device__ __forceinline__ float wredsum(float v) {
#pragma unroll
    for (int o = 16; o; o >>= 1) v += __shfl_xor_sync(0xffffffffu, v, o);
    return v;
}
__device__ __forceinline__ float sgn(float x) {
    return (x > 0.f) ? 1.f : ((x < 0.f) ? -1.f : 0.f);
}
// FMA-only exp for x in [-15, 0]: 2^(x*log2e) with degree-6 Taylor of 2^f
__device__ __forceinline__ float fexp(float x) {
    float t = x * 1.4426950408889634f;
    float fi = floorf(t);
    float f = t - fi;
    float p = 1.5404e-4f;
    p = fmaf(p, f, 1.3333558e-3f);
    p = fmaf(p, f, 9.6181291e-3f);
    p = fmaf(p, f, 5.5504109e-2f);
    p = fmaf(p, f, 2.4022651e-1f);
    p = fmaf(p, f, 6.9314718e-1f);
    p = fmaf(p, f, 1.0f);
    return __int_as_float(((int)fi + 127) << 23) * p;
}

// per-row noise for standalone rows (vfinal only, ~8K rows)
__device__ __forceinline__ void row_noise(int row, int lane, unsigned k0, unsigned k1,
                                          float& nx, float& ny, float& sc) {
    int half = (row >= NPAIR);
    unsigned base = (unsigned)(half ? row - NPAIR : row) * 64u + (unsigned)(lane * 2);
    unsigned a0, a1, b0, b1;
    tf2x32(k0, k1, base, base + HALFC, a0, a1);
    tf2x32(k0, k1, base + 1u, base + 1u + HALFC, b0, b1);
    nx = u32_to_unit(half ? a1 : a0);
    ny = u32_to_unit(half ? b1 : b0);
    sc = EPSC * rsqrtf(wredsum(nx * nx + ny * ny));
}

// warp computes one CSR row (float2 source); 4-wide MLP
__device__ __forceinline__ float2 csr_row(const float* __restrict__ x, int row, int lane) {
    int s = g_rowptr[row], e = g_rowptr[row + 1];
    float ax = 0.f, ay = 0.f, bx = 0.f, by = 0.f;
    float cx = 0.f, cy = 0.f, dx = 0.f, dy = 0.f;
    int i = s;
    for (; i + 3 < e; i += 4) {
        int2 c0 = g_cv[i], c1 = g_cv[i + 1], c2 = g_cv[i + 2], c3 = g_cv[i + 3];
        float2 p0 = ((const float2*)(x + (c0.x << 6)))[lane];
        float2 p1 = ((const float2*)(x + (c1.x << 6)))[lane];
        float2 p2 = ((const float2*)(x + (c2.x << 6)))[lane];
        float2 p3 = ((const float2*)(x + (c3.x << 6)))[lane];
        float v0 = __int_as_float(c0.y), v1 = __int_as_float(c1.y);
        float v2 = __int_as_float(c2.y), v3 = __int_as_float(c3.y);
        ax = fmaf(v0, p0.x, ax); ay = fmaf(v0, p0.y, ay);
        bx = fmaf(v1, p1.x, bx); by = fmaf(v1, p1.y, by);
        cx = fmaf(v2, p2.x, cx); cy = fmaf(v2, p2.y, cy);
        dx = fmaf(v3, p3.x, dx); dy = fmaf(v3, p3.y, dy);
    }
    for (; i < e; i++) {
        int2 c0 = g_cv[i];
        float2 p0 = ((const float2*)(x + (c0.x << 6)))[lane];
        float v0 = __int_as_float(c0.y);
        ax = fmaf(v0, p0.x, ax); ay = fmaf(v0, p0.y, ay);
    }
    return make_float2((ax + bx) + (cx + dx), (ay + by) + (cy + dy));
}

// layer-1 gather directly from the two input embedding arrays
__device__ __forceinline__ float2 csr_row_in(const float* __restrict__ ue,
                                             const float* __restrict__ ie,
                                             int row, int lane) {
    int s = g_rowptr[row], e = g_rowptr[row + 1];
    float ax = 0.f, ay = 0.f, bx = 0.f, by = 0.f;
    float cx = 0.f, cy = 0.f, dx = 0.f, dy = 0.f;
    int i = s;
#define SRC(c) ((c) < N_USERS ? ue + ((c) << 6) : ie + (((c) - N_USERS) << 6))
    for (; i + 3 < e; i += 4) {
        int2 c0 = g_cv[i], c1 = g_cv[i + 1], c2 = g_cv[i + 2], c3 = g_cv[i + 3];
        float2 p0 = ((const float2*)SRC(c0.x))[lane];
        float2 p1 = ((const float2*)SRC(c1.x))[lane];
        float2 p2 = ((const float2*)SRC(c2.x))[lane];
        float2 p3 = ((const float2*)SRC(c3.x))[lane];
        float v0 = __int_as_float(c0.y), v1 = __int_as_float(c1.y);
        float v2 = __int_as_float(c2.y), v3 = __int_as_float(c3.y);
        ax = fmaf(v0, p0.x, ax); ay = fmaf(v0, p0.y, ay);
        bx = fmaf(v1, p1.x, bx); by = fmaf(v1, p1.y, by);
        cx = fmaf(v2, p2.x, cx); cy = fmaf(v2, p2.y, cy);
        dx = fmaf(v3, p3.x, dx); dy = fmaf(v3, p3.y, dy);
    }
    for (; i < e; i++) {
        int2 c0 = g_cv[i];
        float2 p0 = ((const float2*)SRC(c0.x))[lane];
        float v0 = __int_as_float(c0.y);
        ax = fmaf(v0, p0.x, ax); ay = fmaf(v0, p0.y, ay);
    }
#undef SRC
    return make_float2((ax + bx) + (cx + dx), (ay + by) + (cy + dy));
}

// one CSR pass over e1 (float2) + d1 (half4): se = A*e1, sd = A*d1
__device__ __forceinline__ void csr_row_l2(int row, int lane, float2& se, float4& sd) {
    int s = g_rowptr[row], e = g_rowptr[row + 1];
    float ex0 = 0.f, ey0 = 0.f, ex1 = 0.f, ey1 = 0.f;
    float dx0 = 0.f, dy0 = 0.f, dz0 = 0.f, dw0 = 0.f;
    float dx1 = 0.f, dy1 = 0.f, dz1 = 0.f, dw1 = 0.f;
    int i = s;
    for (; i + 3 < e; i += 4) {
        int2 c0 = g_cv[i], c1 = g_cv[i + 1], c2 = g_cv[i + 2], c3 = g_cv[i + 3];
        float2 q0 = ((const float2*)(g_e1 + (c0.x << 6)))[lane];
        float2 q1 = ((const float2*)(g_e1 + (c1.x << 6)))[lane];
        float2 q2 = ((const float2*)(g_e1 + (c2.x << 6)))[lane];
        float2 q3 = ((const float2*)(g_e1 + (c3.x << 6)))[lane];
        uint2 u0 = g_d1[(c0.x << 5) + lane];
        uint2 u1 = g_d1[(c1.x << 5) + lane];
        uint2 u2 = g_d1[(c2.x << 5) + lane];
        uint2 u3 = g_d1[(c3.x << 5) + lane];
        float v0 = __int_as_float(c0.y), v1 = __int_as_float(c1.y);
        float v2 = __int_as_float(c2.y), v3 = __int_as_float(c3.y);
        float4 p0 = unpack4h(u0), p1 = unpack4h(u1), p2 = unpack4h(u2), p3 = unpack4h(u3);
        ex0 = fmaf(v0, q0.x, ex0); ey0 = fmaf(v0, q0.y, ey0);
        ex1 = fmaf(v1, q1.x, ex1); ey1 = fmaf(v1, q1.y, ey1);
        ex0 = fmaf(v2, q2.x, ex0); ey0 = fmaf(v2, q2.y, ey0);
        ex1 = fmaf(v3, q3.x, ex1); ey1 = fmaf(v3, q3.y, ey1);
        dx0 = fmaf(v0, p0.x, dx0); dy0 = fmaf(v0, p0.y, dy0);
        dz0 = fmaf(v0, p0.z, dz0); dw0 = fmaf(v0, p0.w, dw0);
        dx1 = fmaf(v1, p1.x, dx1); dy1 = fmaf(v1, p1.y, dy1);
        dz1 = fmaf(v1, p1.z, dz1); dw1 = fmaf(v1, p1.w, dw1);
        dx0 = fmaf(v2, p2.x, dx0); dy0 = fmaf(v2, p2.y, dy0);
        dz0 = fmaf(v2, p2.z, dz0); dw0 = fmaf(v2, p2.w, dw0);
        dx1 = fmaf(v3, p3.x, dx1); dy1 = fmaf(v3, p3.y, dy1);
        dz1 = fmaf(v3, p3.z, dz1); dw1 = fmaf(v3, p3.w, dw1);
    }
    for (; i < e; i++) {
        int2 c0 = g_cv[i];
        float2 q0 = ((const float2*)(g_e1 + (c0.x << 6)))[lane];
        float4 p0 = unpack4h(g_d1[(c0.x << 5) + lane]);
        float v0 = __int_as_float(c0.y);
        ex0 = fmaf(v0, q0.x, ex0); ey0 = fmaf(v0, q0.y, ey0);
        dx0 = fmaf(v0, p0.x, dx0); dy0 = fmaf(v0, p0.y, dy0);
        dz0 = fmaf(v0, p0.z, dz0); dw0 = fmaf(v0, p0.w, dw0);
    }
    se = make_float2(ex0 + ex1, ey0 + ey1);
    sd = make_float4(dx0 + dx1, dy0 + dy1, dz0 + dz1, dw0 + dw1);
}

// layer-3 view gather: A*(e2 + d2) for one row, both views
__device__ __forceinline__ float4 csr_row_l3(int row, int lane) {
    int s = g_rowptr[row], e = g_rowptr[row + 1];
    float ax = 0.f, ay = 0.f, az = 0.f, aw = 0.f;
    float bx = 0.f, by = 0.f, bz = 0.f, bw = 0.f;
    int i = s;
    for (; i + 1 < e; i += 2) {
        int2 c0 = g_cv[i], c1 = g_cv[i + 1];
        float2 q0 = ((const float2*)(g_e2 + (c0.x << 6)))[lane];
        float2 q1 = ((const float2*)(g_e2 + (c1.x << 6)))[lane];
        float4 p0 = unpack4h(g_d2[(c0.x << 5) + lane]);
        float4 p1 = unpack4h(g_d2[(c1.x << 5) + lane]);
        float v0 = __int_as_float(c0.y), v1 = __int_as_float(c1.y);
        ax = fmaf(v0, q0.x + p0.x, ax); ay = fmaf(v0, q0.y + p0.y, ay);
        az = fmaf(v0, q0.x + p0.z, az); aw = fmaf(v0, q0.y + p0.w, aw);
        bx = fmaf(v1, q1.x + p1.x, bx); by = fmaf(v1, q1.y + p1.y, by);
        bz = fmaf(v1, q1.x + p1.z, bz); bw = fmaf(v1, q1.y + p1.w, bw);
    }
    if (i < e) {
        int2 c0 = g_cv[i];
        float2 q0 = ((const float2*)(g_e2 + (c0.x << 6)))[lane];
        float4 p0 = unpack4h(g_d2[(c0.x << 5) + lane]);
        float v0 = __int_as_float(c0.y);
        ax = fmaf(v0, q0.x + p0.x, ax); ay = fmaf(v0, q0.y + p0.y, ay);
        az = fmaf(v0, q0.x + p0.z, az); aw = fmaf(v0, q0.y + p0.w, aw);
    }
    return make_float4(ax + bx, ay + by, az + bz, aw + bw);
}

// ---------------- setup ----------------
__global__ void k_init() {
    int i = blockIdx.x * blockDim.x + threadIdx.x;
    if (i < N_NODESC) { g_flags[i] = 0; g_counts[i] = 0; }
    if (i < 2 * BATCHC) g_S[i] = 0.f;
    if (i < 8) g_acc[i] = 0.f;
    if (i == 0) { g_ucnt = 0; g_icnt = 0; }
}
__global__ void k_hist(const int* __restrict__ rows) {
    int i = blockIdx.x * blockDim.x + threadIdx.x;
    if (i < NNZC) atomicAdd(&g_counts[rows[i]], 1);
}
__global__ void k_scan1() {
    __shared__ int sh[1024];
    int g = blockIdx.x * 1024 + threadIdx.x;
    int v = (g < N_NODESC) ? g_counts[g] : 0;
    sh[threadIdx.x] = v;
    __syncthreads();
    for (int off = 1; off < 1024; off <<= 1) {
        int t = (threadIdx.x >= off) ? sh[threadIdx.x - off] : 0;
        __syncthreads();
        sh[threadIdx.x] += t;
        __syncthreads();
    }
    if (g < N_NODESC) g_rowptr[g] = sh[threadIdx.x] - v;
    if (threadIdx.x == 1023) g_blocksums[blockIdx.x] = sh[1023];
}
__global__ void k_scan2(int nblocks) {
    __shared__ int sh[256];
    int t = threadIdx.x;
    int v = (t < nblocks) ? g_blocksums[t] : 0;
    sh[t] = v;
    __syncthreads();
    for (int off = 1; off < 256; off <<= 1) {
        int p = (t >= off) ? sh[t - off] : 0;
        __syncthreads();
        sh[t] += p;
        __syncthreads();
    }
    if (t < nblocks) g_blocksums[t] = sh[t] - v;   // exclusive
    if (t == nblocks - 1) g_rowptr[N_NODESC] = sh[t];
}
__global__ void k_scan3() {
    int g = blockIdx.x * blockDim.x + threadIdx.x;
    if (g < N_NODESC) {
        int v = g_rowptr[g] + g_blocksums[g >> 10];
        g_rowptr[g] = v;
        g_cursor[g] = v;
    }
}
__global__ void k_fill(const int* __restrict__ rows, const int* __restrict__ cols,
                       const float* __restrict__ vals) {
    int i = blockIdx.x * blockDim.x + threadIdx.x;
    if (i < NNZC) {
        int p = atomicAdd(&g_cursor[rows[i]], 1);
        g_cv[p] = make_int2(cols[i], __float_as_int(vals[i]));
    }
}

// ---------------- layer 1: e1 = A*[ue;ie]; d1 = fp16 noise offsets (paired tf) ----------------
__global__ void __launch_bounds__(256) k_spmm_e1_noise(const float* __restrict__ ue,
                                                       const float* __restrict__ ie,
                                                       unsigned f10, unsigned f11,
                                                       unsigned f20, unsigned f21) {
    int warp = threadIdx.x >> 5;
    int lane = threadIdx.x & 31;
    int sub = warp & 3;
    int hi = warp >> 2;
    int pr = blockIdx.x * 4 + sub;
    int row = pr + hi * NPAIR;
    __shared__ unsigned shn[2][4][32][2];
    float2 ea = csr_row_in(ue, ie, row, lane);
    unsigned myx[2], myy[2];
    if (!hi) {
        unsigned base = (unsigned)pr * 64u + (unsigned)(lane * 2);
#pragma unroll
        for (int vv = 0; vv < 2; vv++) {
            unsigned k0 = vv ? f20 : f10, k1 = vv ? f21 : f11;
            unsigned a0, a1, b0, b1;
            tf2x32(k0, k1, base, base + HALFC, a0, a1);
            tf2x32(k0, k1, base + 1u, base + 1u + HALFC, b0, b1);
            myx[vv] = a0; myy[vv] = b0;
            shn[vv][sub][lane][0] = a1;
            shn[vv][sub][lane][1] = b1;
        }
    }
    __syncthreads();
    if (hi) {
#pragma unroll
        for (int vv = 0; vv < 2; vv++) {
            myx[vv] = shn[vv][sub][lane][0];
            myy[vv] = shn[vv][sub][lane][1];
        }
    }
    ((float2*)(g_e1 + (row << 6)))[lane] = ea;
    float o1x, o1y, o2x, o2y;
    {
        float nx = u32_to_unit(myx[0]), ny = u32_to_unit(myy[0]);
        float sc = EPSC * rsqrtf(wredsum(nx * nx + ny * ny));
        o1x = sgn(ea.x) * nx * sc;
        o1y = sgn(ea.y) * ny * sc;
    }
    {
        float nx = u32_to_unit(myx[1]), ny = u32_to_unit(myy[1]);
        float sc = EPSC * rsqrtf(wredsum(nx * nx + ny * ny));
        o2x = sgn(ea.x) * nx * sc;
        o2y = sgn(ea.y) * ny * sc;
    }
    g_d1[(row << 5) + lane] = pack4h(o1x, o1y, o2x, o2y);
}

// ---------------- layer 2: e2 = A*e1; d2 = A*d1 + noise2 offsets (paired tf) ----------------
__global__ void __launch_bounds__(256) k_spmm_l2(unsigned f10, unsigned f11,
                                                 unsigned f20, unsigned f21) {
    int warp = threadIdx.x >> 5;
    int lane = threadIdx.x & 31;
    int sub = warp & 3;
    int hi = warp >> 2;
    int pr = blockIdx.x * 4 + sub;
    int row = pr + hi * NPAIR;
    __shared__ unsigned shn[2][4][32][2];
    float2 se;
    float4 sd;
    csr_row_l2(row, lane, se, sd);
    unsigned myx[2], myy[2];
    if (!hi) {
        unsigned base = (unsigned)pr * 64u + (unsigned)(lane * 2);
#pragma unroll
        for (int vv = 0; vv < 2; vv++) {
            unsigned k0 = vv ? f20 : f10, k1 = vv ? f21 : f11;
            unsigned a0, a1, b0, b1;
            tf2x32(k0, k1, base, base + HALFC, a0, a1);
            tf2x32(k0, k1, base + 1u, base + 1u + HALFC, b0, b1);
            myx[vv] = a0; myy[vv] = b0;
            shn[vv][sub][lane][0] = a1;
            shn[vv][sub][lane][1] = b1;
        }
    }
    __syncthreads();
    if (hi) {
#pragma unroll
        for (int vv = 0; vv < 2; vv++) {
            myx[vv] = shn[vv][sub][lane][0];
            myy[vv] = shn[vv][sub][lane][1];
        }
    }
    ((float2*)(g_e2 + (row << 6)))[lane] = se;
    // pre-noise view values: y2pre = se + sd(view parts); noise sign from y2pre
    float y1x = se.x + sd.x, y1y = se.y + sd.y;   // view 1
    float y2x = se.x + sd.z, y2y = se.y + sd.w;   // view 2
    {
        float nx = u32_to_unit(myx[0]), ny = u32_to_unit(myy[0]);
        float sc = EPSC * rsqrtf(wredsum(nx * nx + ny * ny));
        sd.x += sgn(y1x) * nx * sc;
        sd.y += sgn(y1y) * ny * sc;
    }
    {
        float nx = u32_to_unit(myx[1]), ny = u32_to_unit(myy[1]);
        float sc = EPSC * rsqrtf(wredsum(nx * nx + ny * ny));
        sd.z += sgn(y2x) * nx * sc;
        sd.w += sgn(y2y) * ny * sc;
    }
    g_d2[(row << 5) + lane] = pack4h(sd.x, sd.y, sd.z, sd.w);
}

// ---------------- BPR: warp per batch entry, layer-3 rows on the fly ----------------
__global__ void __launch_bounds__(256) k_bpr(const int* __restrict__ ul,
                                             const int* __restrict__ pl,
                                             const int* __restrict__ nl) {
    int w = (blockIdx.x * blockDim.x + threadIdx.x) >> 5;
    int lane = threadIdx.x & 31;
    if (w >= BATCHC) return;
    const float third = 1.f / 3.f;
    int ru = ul[w];
    int rp = N_USERS + pl[w];
    int rn = N_USERS + nl[w];
    float2 u3 = csr_row(g_e2, ru, lane);
    float2 p3 = csr_row(g_e2, rp, lane);
    float2 n3 = csr_row(g_e2, rn, lane);
    float2 u1 = ((const float2*)(g_e1 + (ru << 6)))[lane];
    float2 u2 = ((const float2*)(g_e2 + (ru << 6)))[lane];
    float2 p1 = ((const float2*)(g_e1 + (rp << 6)))[lane];
    float2 p2 = ((const float2*)(g_e2 + (rp << 6)))[lane];
    float2 n1 = ((const float2*)(g_e1 + (rn << 6)))[lane];
    float2 n2 = ((const float2*)(g_e2 + (rn << 6)))[lane];
    float ux = (u1.x + u2.x + u3.x) * third, uy = (u1.y + u2.y + u3.y) * third;
    float px = (p1.x + p2.x + p3.x) * third, py = (p1.y + p2.y + p3.y) * third;
    float nx = (n1.x + n2.x + n3.x) * third, ny = (n1.y + n2.y + n3.y) * third;
    float pos = wredsum(ux * px + uy * py);
    float neg = wredsum(ux * nx + uy * ny);
    float ssu = wredsum(ux * ux + uy * uy);
    float ssp = wredsum(px * px + py * py);
    if (lane == 0) {
        float d = pos - neg;
        float sig = 1.f / (1.f + expf(-d));
        atomicAdd(&g_acc[0], -logf(1e-7f + sig));
        atomicAdd(&g_acc[1], ssu);
        atomicAdd(&g_acc[2], ssp);
    }
}

// ---------------- order-free unique (both lists in one launch) ----------------
__global__ void k_unique2(const int* __restrict__ ul, const int* __restrict__ pl) {
    int i = blockIdx.x * blockDim.x + threadIdx.x;
    if (i >= 2 * BATCHC) return;
    int which = (i >= BATCHC);
    int j = which ? i - BATCHC : i;
    int v = which ? pl[j] : ul[j];
    int fidx = which ? (N_USERS + v) : v;
    if (atomicExch(&g_flags[fidx], 1) == 0) {
        int p = atomicAdd(which ? &g_icnt : &g_ucnt, 1);
        (which ? g_iidx : g_uidx)[p] = v;
    }
}

// ---------------- finalize both views: layer-3 + noise + normalize + pos ----------------
__global__ void __launch_bounds__(256) k_vfinal(unsigned f10, unsigned f11,
                                                unsigned f20, unsigned f21) {
    int w = (blockIdx.x * blockDim.x + threadIdx.x) >> 5;
    int lane = threadIdx.x & 31;
    if (w >= 2 * BATCHC) return;
    int isItem = (w >= BATCHC);
    int j = isItem ? w - BATCHC : w;
    int cnt = isItem ? g_icnt : g_ucnt;
    if (j >= cnt) return;
    int row = isItem ? (N_USERS + g_iidx[j]) : g_uidx[j];
    float4 a3 = csr_row_l3(row, lane);
    float nx, ny, sc;
    row_noise(row, lane, f10, f11, nx, ny, sc);
    a3.x += sgn(a3.x) * nx * sc;
    a3.y += sgn(a3.y) * ny * sc;
    row_noise(row, lane, f20, f21, nx, ny, sc);
    a3.z += sgn(a3.z) * nx * sc;
    a3.w += sgn(a3.w) * ny * sc;
    // reconstruct y1, y2 from e + delta
    float2 e1r = ((const float2*)(g_e1 + (row << 6)))[lane];
    float2 e2r = ((const float2*)(g_e2 + (row << 6)))[lane];
    float4 d1r = unpack4h(g_d1[(row << 5) + lane]);
    float4 d2r = unpack4h(g_d2[(row << 5) + lane]);
    float s1x = (e1r.x + d1r.x) + (e2r.x + d2r.x) + a3.x;
    float s1y = (e1r.y + d1r.y) + (e2r.y + d2r.y) + a3.y;
    float inv1 = rsqrtf(wredsum(s1x * s1x + s1y * s1y));
    s1x *= inv1; s1y *= inv1;
    float s2x = (e1r.x + d1r.z) + (e2r.x + d2r.z) + a3.z;
    float s2y = (e1r.y + d1r.w) + (e2r.y + d2r.w) + a3.w;
    float inv2 = rsqrtf(wredsum(s2x * s2x + s2y * s2y));
    s2x *= inv2; s2y *= inv2;
    g_Vh[0 * 2 + isItem][(j << 5) + lane] = pack2h(s1x, s1y);
    g_Vh[1 * 2 + isItem][(j << 5) + lane] = pack2h(s2x, s2y);
    float d = wredsum(s2x * s1x + s2y * s1y);
    if (lane == 0) (isItem ? g_posI : g_posU)[j] = d * INV_TEMP;
}

// ---------------- InfoNCE via mma.sync (HMMA): warp = m16 x n32 tile ----------------
// g_Vh word layout (word q of row j = cols 2q,2q+1) IS the mma fragment layout:
//   A reg(kb, half h, part t): V1[(rb + l/4 + 8h)*32 + kb*8 + l%4 + 4t]
//   B reg(kb, nt, part t):     V2[(cb + nt*8 + l/4)*32 + kb*8 + l%4 + 4t]
__global__ void __launch_bounds__(256) k_nce() {
    int which = blockIdx.z;
    const unsigned* __restrict__ V1 = g_Vh[0 * 2 + which];
    const unsigned* __restrict__ V2 = g_Vh[1 * 2 + which];
    float* __restrict__ S = g_S + which * BATCHC;
    int U = which ? g_icnt : g_ucnt;
    int warp = threadIdx.x >> 5;
    int lane = threadIdx.x & 31;
    int rb = blockIdx.y * 128 + warp * 16;
    int cb = blockIdx.x * 32;
    if (rb >= U || cb >= U) return;
    int l4 = lane >> 2, lm = lane & 3;
    // A fragments: rows rb+l4 and rb+l4+8, words lm + 4t, t = 0..7 (kb = t/2)
    unsigned a0[8], a1[8];
    {
        const unsigned* A0 = V1 + ((rb + l4) << 5) + lm;
        const unsigned* A1 = V1 + ((rb + l4 + 8) << 5) + lm;
#pragma unroll
        for (int t = 0; t < 8; t++) { a0[t] = A0[4 * t]; a1[t] = A1[4 * t]; }
    }
    float ssum0 = 0.f, ssum1 = 0.f;   // row sums for rows rb+l4, rb+l4+8
#pragma unroll
    for (int nt = 0; nt < 4; nt++) {
        int col0 = cb + nt * 8;
        unsigned b[8];
        const unsigned* B0 = V2 + ((col0 + l4) << 5) + lm;
#pragma unroll
        for (int t = 0; t < 8; t++) b[t] = B0[4 * t];
        float c0 = 0.f, c1 = 0.f, c2 = 0.f, c3 = 0.f;
#pragma unroll
        for (int kb = 0; kb < 4; kb++) {
            asm volatile(
                "mma.sync.aligned.m16n8k16.row.col.f32.f16.f16.f32 "
                "{%0,%1,%2,%3}, {%4,%5,%6,%7}, {%8,%9}, {%0,%1,%2,%3};"
                : "+f"(c0), "+f"(c1), "+f"(c2), "+f"(c3)
                : "r"(a0[2 * kb]), "r"(a1[2 * kb]),
                  "r"(a0[2 * kb + 1]), "r"(a1[2 * kb + 1]),
                  "r"(b[2 * kb]), "r"(b[2 * kb + 1]));
        }
        // C layout: c0,c1 = (row rb+l4, cols col0+lm*2, +1); c2,c3 = (row rb+l4+8, same cols)
        int cA = col0 + lm * 2, cB = cA + 1;
        if (cA < U) { ssum0 += fexp(fmaf(c0, INV_TEMP, -5.0f));
                      ssum1 += fexp(fmaf(c2, INV_TEMP, -5.0f)); }
        if (cB < U) { ssum0 += fexp(fmaf(c1, INV_TEMP, -5.0f));
                      ssum1 += fexp(fmaf(c3, INV_TEMP, -5.0f)); }
    }
    // reduce across the 4 lanes of each row group (lanes l4*4 + lm)
#pragma unroll
    for (int o = 1; o < 4; o <<= 1) {
        ssum0 += __shfl_xor_sync(0xffffffffu, ssum0, o);
        ssum1 += __shfl_xor_sync(0xffffffffu, ssum1, o);
    }
    if (lm == 0) {
        if (rb + l4 < U)     atomicAdd(&S[rb + l4], ssum0);
        if (rb + l4 + 8 < U) atomicAdd(&S[rb + l4 + 8], ssum1);
    }
}

__global__ void __launch_bounds__(256) k_ncefin() {
    int i = blockIdx.x * blockDim.x + threadIdx.x;
    int which = (i >= BATCHC);
    int j = i - which * BATCHC;
    int U = which ? g_icnt : g_ucnt;
    float c = 0.f;
    if (i < 2 * BATCHC && j < U)
        c = 5.0f + logf(g_S[i]) - (which ? g_posI[j] : g_posU[j]);
    c = wredsum(c);
    if ((threadIdx.x & 31) == 0 && c != 0.f)
        atomicAdd(&g_acc[3 + which], c);
}

__global__ void k_final(float* out) {
    if (threadIdx.x == 0) {
        float rec = g_acc[0] / (float)BATCHC;
        float reg = 1e-4f * (sqrtf(g_acc[1]) + sqrtf(g_acc[2]));
        float cl = 0.2f * (g_acc[3] / (float)g_ucnt + g_acc[4] / (float)g_icnt);
        out[0] = rec + reg + cl;
        out[1] = cl;
    }
}

// ---------------- launch ----------------
extern "C" void kernel_launch(void* const* d_in, const int* in_sizes, int n_in,
                              void* d_out, int out_size) {
    const float* ue = (const float*)d_in[0];
    const float* ie = (const float*)d_in[1];
    const float* av = (const float*)d_in[2];
    const int*   ar = (const int*)d_in[3];
    const int*   ac = (const int*)d_in[4];
    const int*   ul = (const int*)d_in[5];
    const int*   pl = (const int*)d_in[6];
    const int*   nl = (const int*)d_in[7];
    float* out = (float*)d_out;

    const int SCAN_BLOCKS = (N_NODESC + 1023) / 1024;
    const int PAIRED_BLOCKS = NPAIR / 4;   // 18750: 4 row-pairs per 8-warp block

    unsigned seeds[2] = {101u, 202u};
    unsigned fk[2][3][2];
    for (int vv = 0; vv < 2; vv++)
        for (int k = 0; k < 3; k++)
            tf2x32(0u, seeds[vv], 0u, (unsigned)k, fk[vv][k][0], fk[vv][k][1]);

    k_init<<<(N_NODESC + 255) / 256, 256>>>();
    k_hist<<<(NNZC + 255) / 256, 256>>>(ar);
    k_scan1<<<SCAN_BLOCKS, 1024>>>();
    k_scan2<<<1, 256>>>(SCAN_BLOCKS);
    k_scan3<<<SCAN_BLOCKS, 1024>>>();
    k_fill<<<(NNZC + 255) / 256, 256>>>(ar, ac, av);
    k_unique2<<<(2 * BATCHC + 255) / 256, 256>>>(ul, pl);

    // layer 1: e1 + fp16 noise deltas (paired tf)
    k_spmm_e1_noise<<<PAIRED_BLOCKS, 256>>>(ue, ie,
        fk[0][0][0], fk[0][0][1], fk[1][0][0], fk[1][0][1]);
    // layer 2: e2 = A*e1 and d2 = A*d1 + noise2, L2-resident gathers
    k_spmm_l2<<<PAIRED_BLOCKS, 256>>>(fk[0][1][0], fk[0][1][1], fk[1][1][0], fk[1][1][1]);
    k_bpr<<<(BATCHC * 32) / 256, 256>>>(ul, pl, nl);
    k_vfinal<<<(2 * BATCHC * 32) / 256, 256>>>(fk[0][2][0], fk[0][2][1], fk[1][2][0], fk[1][2][1]);

    dim3 nce_grid(BATCHC / 32, BATCHC / 128, 2);   // (128, 32, 2), 8 warps/block
    k_nce<<<nce_grid, 256>>>();
    k_ncefin<<<(2 * BATCHC + 255) / 256, 256>>>();
    k_final<<<1, 32>>>(out);
}

// round 15
// speedup vs baseline: 1.2111x; 1.0086x over previous
#include <cuda_runtime.h>
#include <cuda_fp16.h>
#include <cstdint>

#define N_USERS 100000
#define N_ITEMS 50000
#define N_NODESC 150000
#define NNZC 2400000
#define DIM 64
#define BATCHC 4096
#define HALFC 4800000u
#define NPAIR 75000
#define EPSC 0.1f
#define INV_TEMP 5.0f

// ---------------- static device scratch (allocation-free) ----------------
// AoS records: one 16B load per gathered node per lane.
// c1: {e1x bits, e1y bits, d1 half4 (v1x,v1y | v2x,v2y)}
// c2: {e2x bits, e2y bits, d2 half4}
__device__ uint4  g_c1 [N_NODESC * 32];
__device__ uint4  g_c2 [N_NODESC * 32];
__device__ int2   g_cv[NNZC];
__device__ int    g_rowptr[N_NODESC + 1];
__device__ int    g_cursor[N_NODESC];
__device__ int    g_counts[N_NODESC];
__device__ int    g_blocksums[256];
__device__ int    g_flags[N_NODESC];
__device__ int    g_uidx[BATCHC];
__device__ int    g_iidx[BATCHC];
__device__ int    g_ucnt;
__device__ int    g_icnt;
__device__ unsigned g_Vh[4][BATCHC * 32]; // half2-packed normalized views
__device__ float  g_posU[BATCHC], g_posI[BATCHC];
__device__ float  g_S[2 * BATCHC];
__device__ float  g_acc[8];               // 0 rec, 1 ssu, 2 ssp

// ---------------- half pack/unpack ----------------
__device__ __forceinline__ uint2 pack4h(float a, float b, float c, float d) {
    __half2 lo = __floats2half2_rn(a, b);
    __half2 hi = __floats2half2_rn(c, d);
    uint2 r;
    r.x = *(const unsigned*)&lo;
    r.y = *(const unsigned*)&hi;
    return r;
}
__device__ __forceinline__ float4 unpack4h2(unsigned lo, unsigned hi) {
    float2 l = __half22float2(*(const __half2*)&lo);
    float2 h = __half22float2(*(const __half2*)&hi);
    return make_float4(l.x, l.y, h.x, h.y);
}
__device__ __forceinline__ unsigned pack2h(float a, float b) {
    __half2 h = __floats2half2_rn(a, b);
    return *(const unsigned*)&h;
}

// ---------------- threefry-2x32 (exact JAX schedule) ----------------
__host__ __device__ __forceinline__ unsigned rl32(unsigned x, int r) {
    return (x << r) | (x >> (32 - r));
}
__host__ __device__ __forceinline__ void tf2x32(unsigned k0, unsigned k1,
                                                unsigned x0, unsigned x1,
                                                unsigned& o0, unsigned& o1) {
    unsigned k2 = k0 ^ k1 ^ 0x1BD11BDAu;
    x0 += k0; x1 += k1;
#define TFR(r) { x0 += x1; x1 = rl32(x1, r); x1 ^= x0; }
    TFR(13) TFR(15) TFR(26) TFR(6)
    x0 += k1; x1 += k2 + 1u;
    TFR(17) TFR(29) TFR(16) TFR(24)
    x0 += k2; x1 += k0 + 2u;
    TFR(13) TFR(15) TFR(26) TFR(6)
    x0 += k0; x1 += k1 + 3u;
    TFR(17) TFR(29) TFR(16) TFR(24)
    x0 += k1; x1 += k2 + 4u;
    TFR(13) TFR(15) TFR(26) TFR(6)
    x0 += k2; x1 += k0 + 5u;
#undef TFR
    o0 = x0; o1 = x1;
}
__device__ __forceinline__ float u32_to_unit(unsigned b) {
    return __uint_as_float((b >> 9) | 0x3f800000u) - 1.0f;
}
__device__ __forceinline__ float wredsum(float v) {
#pragma unroll
    for (int o = 16; o; o >>= 1) v += __shfl_xor_sync(0xffffffffu, v, o);
    return v;
}
__device__ __forceinline__ float sgn(float x) {
    return (x > 0.f) ? 1.f : ((x < 0.f) ? -1.f : 0.f);
}
// FMA-only exp for x in [-15, 0]
__device__ __forceinline__ float fexp(float x) {
    float t = x * 1.4426950408889634f;
    float fi = floorf(t);
    float f = t - fi;
    float p = 1.5404e-4f;
    p = fmaf(p, f, 1.3333558e-3f);
    p = fmaf(p, f, 9.6181291e-3f);
    p = fmaf(p, f, 5.5504109e-2f);
    p = fmaf(p, f, 2.4022651e-1f);
    p = fmaf(p, f, 6.9314718e-1f);
    p = fmaf(p, f, 1.0f);
    return __int_as_float(((int)fi + 127) << 23) * p;
}

// per-row noise for standalone rows (vfinal only, ~8K rows)
__device__ __forceinline__ void row_noise(int row, int lane, unsigned k0, unsigned k1,
                                          float& nx, float& ny, float& sc) {
    int half = (row >= NPAIR);
    unsigned base = (unsigned)(half ? row - NPAIR : row) * 64u + (unsigned)(lane * 2);
    unsigned a0, a1, b0, b1;
    tf2x32(k0, k1, base, base + HALFC, a0, a1);
    tf2x32(k0, k1, base + 1u, base + 1u + HALFC, b0, b1);
    nx = u32_to_unit(half ? a1 : a0);
    ny = u32_to_unit(half ? b1 : b0);
    sc = EPSC * rsqrtf(wredsum(nx * nx + ny * ny));
}

// layer-1 gather directly from the two input embedding arrays
__device__ __forceinline__ float2 csr_row_in(const float* __restrict__ ue,
                                             const float* __restrict__ ie,
                                             int row, int lane) {
    int s = g_rowptr[row], e = g_rowptr[row + 1];
    float ax = 0.f, ay = 0.f, bx = 0.f, by = 0.f;
    float cx = 0.f, cy = 0.f, dx = 0.f, dy = 0.f;
    int i = s;
#define SRC(c) ((c) < N_USERS ? ue + ((c) << 6) : ie + (((c) - N_USERS) << 6))
    for (; i + 3 < e; i += 4) {
        int2 c0 = g_cv[i], c1 = g_cv[i + 1], c2 = g_cv[i + 2], c3 = g_cv[i + 3];
        float2 p0 = ((const float2*)SRC(c0.x))[lane];
        float2 p1 = ((const float2*)SRC(c1.x))[lane];
        float2 p2 = ((const float2*)SRC(c2.x))[lane];
        float2 p3 = ((const float2*)SRC(c3.x))[lane];
        float v0 = __int_as_float(c0.y), v1 = __int_as_float(c1.y);
        float v2 = __int_as_float(c2.y), v3 = __int_as_float(c3.y);
        ax = fmaf(v0, p0.x, ax); ay = fmaf(v0, p0.y, ay);
        bx = fmaf(v1, p1.x, bx); by = fmaf(v1, p1.y, by);
        cx = fmaf(v2, p2.x, cx); cy = fmaf(v2, p2.y, cy);
        dx = fmaf(v3, p3.x, dx); dy = fmaf(v3, p3.y, dy);
    }
    for (; i < e; i++) {
        int2 c0 = g_cv[i];
        float2 p0 = ((const float2*)SRC(c0.x))[lane];
        float v0 = __int_as_float(c0.y);
        ax = fmaf(v0, p0.x, ax); ay = fmaf(v0, p0.y, ay);
    }
#undef SRC
    return make_float2((ax + bx) + (cx + dx), (ay + by) + (cy + dy));
}

// one CSR pass over c1 (AoS 16B): se = A*e1, sd = A*d1 — ONE LDG.128 per nnz/lane
__device__ __forceinline__ void csr_row_l2(int row, int lane, float2& se, float4& sd) {
    int s = g_rowptr[row], e = g_rowptr[row + 1];
    float ex0 = 0.f, ey0 = 0.f, ex1 = 0.f, ey1 = 0.f;
    float dx0 = 0.f, dy0 = 0.f, dz0 = 0.f, dw0 = 0.f;
    float dx1 = 0.f, dy1 = 0.f, dz1 = 0.f, dw1 = 0.f;
    int i = s;
    for (; i + 3 < e; i += 4) {
        int2 c0 = g_cv[i], c1 = g_cv[i + 1], c2 = g_cv[i + 2], c3 = g_cv[i + 3];
        uint4 u0 = g_c1[(c0.x << 5) + lane];
        uint4 u1 = g_c1[(c1.x << 5) + lane];
        uint4 u2 = g_c1[(c2.x << 5) + lane];
        uint4 u3 = g_c1[(c3.x << 5) + lane];
        float v0 = __int_as_float(c0.y), v1 = __int_as_float(c1.y);
        float v2 = __int_as_float(c2.y), v3 = __int_as_float(c3.y);
        float4 p0 = unpack4h2(u0.z, u0.w), p1 = unpack4h2(u1.z, u1.w);
        float4 p2 = unpack4h2(u2.z, u2.w), p3 = unpack4h2(u3.z, u3.w);
        ex0 = fmaf(v0, __int_as_float(u0.x), ex0); ey0 = fmaf(v0, __int_as_float(u0.y), ey0);
        ex1 = fmaf(v1, __int_as_float(u1.x), ex1); ey1 = fmaf(v1, __int_as_float(u1.y), ey1);
        ex0 = fmaf(v2, __int_as_float(u2.x), ex0); ey0 = fmaf(v2, __int_as_float(u2.y), ey0);
        ex1 = fmaf(v3, __int_as_float(u3.x), ex1); ey1 = fmaf(v3, __int_as_float(u3.y), ey1);
        dx0 = fmaf(v0, p0.x, dx0); dy0 = fmaf(v0, p0.y, dy0);
        dz0 = fmaf(v0, p0.z, dz0); dw0 = fmaf(v0, p0.w, dw0);
        dx1 = fmaf(v1, p1.x, dx1); dy1 = fmaf(v1, p1.y, dy1);
        dz1 = fmaf(v1, p1.z, dz1); dw1 = fmaf(v1, p1.w, dw1);
        dx0 = fmaf(v2, p2.x, dx0); dy0 = fmaf(v2, p2.y, dy0);
        dz0 = fmaf(v2, p2.z, dz0); dw0 = fmaf(v2, p2.w, dw0);
        dx1 = fmaf(v3, p3.x, dx1); dy1 = fmaf(v3, p3.y, dy1);
        dz1 = fmaf(v3, p3.z, dz1); dw1 = fmaf(v3, p3.w, dw1);
    }
    for (; i < e; i++) {
        int2 c0 = g_cv[i];
        uint4 u0 = g_c1[(c0.x << 5) + lane];
        float4 p0 = unpack4h2(u0.z, u0.w);
        float v0 = __int_as_float(c0.y);
        ex0 = fmaf(v0, __int_as_float(u0.x), ex0); ey0 = fmaf(v0, __int_as_float(u0.y), ey0);
        dx0 = fmaf(v0, p0.x, dx0); dy0 = fmaf(v0, p0.y, dy0);
        dz0 = fmaf(v0, p0.z, dz0); dw0 = fmaf(v0, p0.w, dw0);
    }
    se = make_float2(ex0 + ex1, ey0 + ey1);
    sd = make_float4(dx0 + dx1, dy0 + dy1, dz0 + dz1, dw0 + dw1);
}

// BPR layer-3: gather e2 only from c2 (uses .x/.y of the 16B record)
__device__ __forceinline__ float2 csr_row_e2(int row, int lane) {
    int s = g_rowptr[row], e = g_rowptr[row + 1];
    float ax = 0.f, ay = 0.f, bx = 0.f, by = 0.f;
    float cx = 0.f, cy = 0.f, dx = 0.f, dy = 0.f;
    int i = s;
    for (; i + 3 < e; i += 4) {
        int2 c0 = g_cv[i], c1 = g_cv[i + 1], c2 = g_cv[i + 2], c3 = g_cv[i + 3];
        uint2 p0 = *(const uint2*)&g_c1[0];   // placeholder to keep layout; replaced below
        (void)p0;
        uint2 q0 = *(const uint2*)&g_c2[(c0.x << 5) + lane];
        uint2 q1 = *(const uint2*)&g_c2[(c1.x << 5) + lane];
        uint2 q2 = *(const uint2*)&g_c2[(c2.x << 5) + lane];
        uint2 q3 = *(const uint2*)&g_c2[(c3.x << 5) + lane];
        float v0 = __int_as_float(c0.y), v1 = __int_as_float(c1.y);
        float v2 = __int_as_float(c2.y), v3 = __int_as_float(c3.y);
        ax = fmaf(v0, __int_as_float(q0.x), ax); ay = fmaf(v0, __int_as_float(q0.y), ay);
        bx = fmaf(v1, __int_as_float(q1.x), bx); by = fmaf(v1, __int_as_float(q1.y), by);
        cx = fmaf(v2, __int_as_float(q2.x), cx); cy = fmaf(v2, __int_as_float(q2.y), cy);
        dx = fmaf(v3, __int_as_float(q3.x), dx); dy = fmaf(v3, __int_as_float(q3.y), dy);
    }
    for (; i < e; i++) {
        int2 c0 = g_cv[i];
        uint2 q0 = *(const uint2*)&g_c2[(c0.x << 5) + lane];
        float v0 = __int_as_float(c0.y);
        ax = fmaf(v0, __int_as_float(q0.x), ax); ay = fmaf(v0, __int_as_float(q0.y), ay);
    }
    return make_float2((ax + bx) + (cx + dx), (ay + by) + (cy + dy));
}

// layer-3 view gather: A*(e2 + d2) for one row, both views — ONE LDG.128 per nnz/lane
__device__ __forceinline__ float4 csr_row_l3(int row, int lane) {
    int s = g_rowptr[row], e = g_rowptr[row + 1];
    float ax = 0.f, ay = 0.f, az = 0.f, aw = 0.f;
    float bx = 0.f, by = 0.f, bz = 0.f, bw = 0.f;
    int i = s;
    for (; i + 1 < e; i += 2) {
        int2 c0 = g_cv[i], c1 = g_cv[i + 1];
        uint4 u0 = g_c2[(c0.x << 5) + lane];
        uint4 u1 = g_c2[(c1.x << 5) + lane];
        float4 p0 = unpack4h2(u0.z, u0.w);
        float4 p1 = unpack4h2(u1.z, u1.w);
        float e0x = __int_as_float(u0.x), e0y = __int_as_float(u0.y);
        float e1x = __int_as_float(u1.x), e1y = __int_as_float(u1.y);
        float v0 = __int_as_float(c0.y), v1 = __int_as_float(c1.y);
        ax = fmaf(v0, e0x + p0.x, ax); ay = fmaf(v0, e0y + p0.y, ay);
        az = fmaf(v0, e0x + p0.z, az); aw = fmaf(v0, e0y + p0.w, aw);
        bx = fmaf(v1, e1x + p1.x, bx); by = fmaf(v1, e1y + p1.y, by);
        bz = fmaf(v1, e1x + p1.z, bz); bw = fmaf(v1, e1y + p1.w, bw);
    }
    if (i < e) {
        int2 c0 = g_cv[i];
        uint4 u0 = g_c2[(c0.x << 5) + lane];
        float4 p0 = unpack4h2(u0.z, u0.w);
        float e0x = __int_as_float(u0.x), e0y = __int_as_float(u0.y);
        float v0 = __int_as_float(c0.y);
        ax = fmaf(v0, e0x + p0.x, ax); ay = fmaf(v0, e0y + p0.y, ay);
        az = fmaf(v0, e0x + p0.z, az); aw = fmaf(v0, e0y + p0.w, aw);
    }
    return make_float4(ax + bx, ay + by, az + bz, aw + bw);
}

// ---------------- setup ----------------
__global__ void k_init() {
    int i = blockIdx.x * blockDim.x + threadIdx.x;
    if (i < N_NODESC) { g_flags[i] = 0; g_counts[i] = 0; }
    if (i < 2 * BATCHC) g_S[i] = 0.f;
    if (i < 8) g_acc[i] = 0.f;
    if (i == 0) { g_ucnt = 0; g_icnt = 0; }
}
__global__ void k_hist(const int* __restrict__ rows) {
    int i = blockIdx.x * blockDim.x + threadIdx.x;
    if (i < NNZC) atomicAdd(&g_counts[rows[i]], 1);
}
__global__ void k_scan1() {
    __shared__ int sh[1024];
    int g = blockIdx.x * 1024 + threadIdx.x;
    int v = (g < N_NODESC) ? g_counts[g] : 0;
    sh[threadIdx.x] = v;
    __syncthreads();
    for (int off = 1; off < 1024; off <<= 1) {
        int t = (threadIdx.x >= off) ? sh[threadIdx.x - off] : 0;
        __syncthreads();
        sh[threadIdx.x] += t;
        __syncthreads();
    }
    if (g < N_NODESC) g_rowptr[g] = sh[threadIdx.x] - v;
    if (threadIdx.x == 1023) g_blocksums[blockIdx.x] = sh[1023];
}
__global__ void k_scan2(int nblocks) {
    __shared__ int sh[256];
    int t = threadIdx.x;
    int v = (t < nblocks) ? g_blocksums[t] : 0;
    sh[t] = v;
    __syncthreads();
    for (int off = 1; off < 256; off <<= 1) {
        int p = (t >= off) ? sh[t - off] : 0;
        __syncthreads();
        sh[t] += p;
        __syncthreads();
    }
    if (t < nblocks) g_blocksums[t] = sh[t] - v;
    if (t == nblocks - 1) g_rowptr[N_NODESC] = sh[t];
}
__global__ void k_scan3() {
    int g = blockIdx.x * blockDim.x + threadIdx.x;
    if (g < N_NODESC) {
        int v = g_rowptr[g] + g_blocksums[g >> 10];
        g_rowptr[g] = v;
        g_cursor[g] = v;
    }
}
__global__ void k_fill(const int* __restrict__ rows, const int* __restrict__ cols,
                       const float* __restrict__ vals) {
    int i = blockIdx.x * blockDim.x + threadIdx.x;
    if (i < NNZC) {
        int p = atomicAdd(&g_cursor[rows[i]], 1);
        g_cv[p] = make_int2(cols[i], __float_as_int(vals[i]));
    }
}

// ---------------- layer 1: c1 = {e1 = A*[ue;ie], d1 = noise offsets} (paired tf) ----------------
__global__ void __launch_bounds__(256) k_spmm_e1_noise(const float* __restrict__ ue,
                                                       const float* __restrict__ ie,
                                                       unsigned f10, unsigned f11,
                                                       unsigned f20, unsigned f21) {
    int warp = threadIdx.x >> 5;
    int lane = threadIdx.x & 31;
    int sub = warp & 3;
    int hi = warp >> 2;
    int pr = blockIdx.x * 4 + sub;
    int row = pr + hi * NPAIR;
    __shared__ unsigned shn[2][4][32][2];
    float2 ea = csr_row_in(ue, ie, row, lane);
    unsigned myx[2], myy[2];
    if (!hi) {
        unsigned base = (unsigned)pr * 64u + (unsigned)(lane * 2);
#pragma unroll
        for (int vv = 0; vv < 2; vv++) {
            unsigned k0 = vv ? f20 : f10, k1 = vv ? f21 : f11;
            unsigned a0, a1, b0, b1;
            tf2x32(k0, k1, base, base + HALFC, a0, a1);
            tf2x32(k0, k1, base + 1u, base + 1u + HALFC, b0, b1);
            myx[vv] = a0; myy[vv] = b0;
            shn[vv][sub][lane][0] = a1;
            shn[vv][sub][lane][1] = b1;
        }
    }
    __syncthreads();
    if (hi) {
#pragma unroll
        for (int vv = 0; vv < 2; vv++) {
            myx[vv] = shn[vv][sub][lane][0];
            myy[vv] = shn[vv][sub][lane][1];
        }
    }
    float o1x, o1y, o2x, o2y;
    {
        float nx = u32_to_unit(myx[0]), ny = u32_to_unit(myy[0]);
        float sc = EPSC * rsqrtf(wredsum(nx * nx + ny * ny));
        o1x = sgn(ea.x) * nx * sc;
        o1y = sgn(ea.y) * ny * sc;
    }
    {
        float nx = u32_to_unit(myx[1]), ny = u32_to_unit(myy[1]);
        float sc = EPSC * rsqrtf(wredsum(nx * nx + ny * ny));
        o2x = sgn(ea.x) * nx * sc;
        o2y = sgn(ea.y) * ny * sc;
    }
    uint2 dh = pack4h(o1x, o1y, o2x, o2y);
    g_c1[(row << 5) + lane] = make_uint4(__float_as_int(ea.x), __float_as_int(ea.y), dh.x, dh.y);
}

// ---------------- layer 2: c2 = {e2 = A*e1, d2 = A*d1 + noise2} (paired tf) ----------------
__global__ void __launch_bounds__(256) k_spmm_l2(unsigned f10, unsigned f11,
                                                 unsigned f20, unsigned f21) {
    int warp = threadIdx.x >> 5;
    int lane = threadIdx.x & 31;
    int sub = warp & 3;
    int hi = warp >> 2;
    int pr = blockIdx.x * 4 + sub;
    int row = pr + hi * NPAIR;
    __shared__ unsigned shn[2][4][32][2];
    float2 se;
    float4 sd;
    csr_row_l2(row, lane, se, sd);
    unsigned myx[2], myy[2];
    if (!hi) {
        unsigned base = (unsigned)pr * 64u + (unsigned)(lane * 2);
#pragma unroll
        for (int vv = 0; vv < 2; vv++) {
            unsigned k0 = vv ? f20 : f10, k1 = vv ? f21 : f11;
            unsigned a0, a1, b0, b1;
            tf2x32(k0, k1, base, base + HALFC, a0, a1);
            tf2x32(k0, k1, base + 1u, base + 1u + HALFC, b0, b1);
            myx[vv] = a0; myy[vv] = b0;
            shn[vv][sub][lane][0] = a1;
            shn[vv][sub][lane][1] = b1;
        }
    }
    __syncthreads();
    if (hi) {
#pragma unroll
        for (int vv = 0; vv < 2; vv++) {
            myx[vv] = shn[vv][sub][lane][0];
            myy[vv] = shn[vv][sub][lane][1];
        }
    }
    float y1x = se.x + sd.x, y1y = se.y + sd.y;
    float y2x = se.x + sd.z, y2y = se.y + sd.w;
    {
        float nx = u32_to_unit(myx[0]), ny = u32_to_unit(myy[0]);
        float sc = EPSC * rsqrtf(wredsum(nx * nx + ny * ny));
        sd.x += sgn(y1x) * nx * sc;
        sd.y += sgn(y1y) * ny * sc;
    }
    {
        float nx = u32_to_unit(myx[1]), ny = u32_to_unit(myy[1]);
        float sc = EPSC * rsqrtf(wredsum(nx * nx + ny * ny));
        sd.z += sgn(y2x) * nx * sc;
        sd.w += sgn(y2y) * ny * sc;
    }
    uint2 dh = pack4h(sd.x, sd.y, sd.z, sd.w);
    g_c2[(row << 5) + lane] = make_uint4(__float_as_int(se.x), __float_as_int(se.y), dh.x, dh.y);
}

// ---------------- BPR: warp per batch entry, layer-3 rows on the fly ----------------
__global__ void __launch_bounds__(256) k_bpr(const int* __restrict__ ul,
                                             const int* __restrict__ pl,
                                             const int* __restrict__ nl) {
    int w = (blockIdx.x * blockDim.x + threadIdx.x) >> 5;
    int lane = threadIdx.x & 31;
    if (w >= BATCHC) return;
    const float third = 1.f / 3.f;
    int ru = ul[w];
    int rp = N_USERS + pl[w];
    int rn = N_USERS + nl[w];
    float2 u3 = csr_row_e2(ru, lane);
    float2 p3 = csr_row_e2(rp, lane);
    float2 n3 = csr_row_e2(rn, lane);
    uint4 uc1 = g_c1[(ru << 5) + lane], uc2 = g_c2[(ru << 5) + lane];
    uint4 pc1 = g_c1[(rp << 5) + lane], pc2 = g_c2[(rp << 5) + lane];
    uint4 nc1 = g_c1[(rn << 5) + lane], nc2 = g_c2[(rn << 5) + lane];
    float ux = (__int_as_float(uc1.x) + __int_as_float(uc2.x) + u3.x) * third;
    float uy = (__int_as_float(uc1.y) + __int_as_float(uc2.y) + u3.y) * third;
    float px = (__int_as_float(pc1.x) + __int_as_float(pc2.x) + p3.x) * third;
    float py = (__int_as_float(pc1.y) + __int_as_float(pc2.y) + p3.y) * third;
    float nx = (__int_as_float(nc1.x) + __int_as_float(nc2.x) + n3.x) * third;
    float ny = (__int_as_float(nc1.y) + __int_as_float(nc2.y) + n3.y) * third;
    float pos = wredsum(ux * px + uy * py);
    float neg = wredsum(ux * nx + uy * ny);
    float ssu = wredsum(ux * ux + uy * uy);
    float ssp = wredsum(px * px + py * py);
    if (lane == 0) {
        float d = pos - neg;
        float sig = 1.f / (1.f + expf(-d));
        atomicAdd(&g_acc[0], -logf(1e-7f + sig));
        atomicAdd(&g_acc[1], ssu);
        atomicAdd(&g_acc[2], ssp);
    }
}

// ---------------- order-free unique (both lists in one launch) ----------------
__global__ void k_unique2(const int* __restrict__ ul, const int* __restrict__ pl) {
    int i = blockIdx.x * blockDim.x + threadIdx.x;
    if (i >= 2 * BATCHC) return;
    int which = (i >= BATCHC);
    int j = which ? i - BATCHC : i;
    int v = which ? pl[j] : ul[j];
    int fidx = which ? (N_USERS + v) : v;
    if (atomicExch(&g_flags[fidx], 1) == 0) {
        int p = atomicAdd(which ? &g_icnt : &g_ucnt, 1);
        (which ? g_iidx : g_uidx)[p] = v;
    }
}

// ---------------- finalize both views: layer-3 + noise + normalize + pos ----------------
__global__ void __launch_bounds__(256) k_vfinal(unsigned f10, unsigned f11,
                                                unsigned f20, unsigned f21) {
    int w = (blockIdx.x * blockDim.x + threadIdx.x) >> 5;
    int lane = threadIdx.x & 31;
    if (w >= 2 * BATCHC) return;
    int isItem = (w >= BATCHC);
    int j = isItem ? w - BATCHC : w;
    int cnt = isItem ? g_icnt : g_ucnt;
    if (j >= cnt) return;
    int row = isItem ? (N_USERS + g_iidx[j]) : g_uidx[j];
    float4 a3 = csr_row_l3(row, lane);
    float nx, ny, sc;
    row_noise(row, lane, f10, f11, nx, ny, sc);
    a3.x += sgn(a3.x) * nx * sc;
    a3.y += sgn(a3.y) * ny * sc;
    row_noise(row, lane, f20, f21, nx, ny, sc);
    a3.z += sgn(a3.z) * nx * sc;
    a3.w += sgn(a3.w) * ny * sc;
    uint4 c1r = g_c1[(row << 5) + lane];
    uint4 c2r = g_c2[(row << 5) + lane];
    float e1x = __int_as_float(c1r.x), e1y = __int_as_float(c1r.y);
    float e2x = __int_as_float(c2r.x), e2y = __int_as_float(c2r.y);
    float4 d1r = unpack4h2(c1r.z, c1r.w);
    float4 d2r = unpack4h2(c2r.z, c2r.w);
    float s1x = (e1x + d1r.x) + (e2x + d2r.x) + a3.x;
    float s1y = (e1y + d1r.y) + (e2y + d2r.y) + a3.y;
    float inv1 = rsqrtf(wredsum(s1x * s1x + s1y * s1y));
    s1x *= inv1; s1y *= inv1;
    float s2x = (e1x + d1r.z) + (e2x + d2r.z) + a3.z;
    float s2y = (e1y + d1r.w) + (e2y + d2r.w) + a3.w;
    float inv2 = rsqrtf(wredsum(s2x * s2x + s2y * s2y));
    s2x *= inv2; s2y *= inv2;
    g_Vh[0 * 2 + isItem][(j << 5) + lane] = pack2h(s1x, s1y);
    g_Vh[1 * 2 + isItem][(j << 5) + lane] = pack2h(s2x, s2y);
    float d = wredsum(s2x * s1x + s2y * s1y);
    if (lane == 0) (isItem ? g_posI : g_posU)[j] = d * INV_TEMP;
}

// ---------------- InfoNCE via mma.sync (HMMA): warp = m16 x n32 tile ----------------
__global__ void __launch_bounds__(256) k_nce() {
    int which = blockIdx.z;
    const unsigned* __restrict__ V1 = g_Vh[0 * 2 + which];
    const unsigned* __restrict__ V2 = g_Vh[1 * 2 + which];
    float* __restrict__ S = g_S + which * BATCHC;
    int U = which ? g_icnt : g_ucnt;
    int warp = threadIdx.x >> 5;
    int lane = threadIdx.x & 31;
    int rb = blockIdx.y * 128 + warp * 16;
    int cb = blockIdx.x * 32;
    if (rb >= U || cb >= U) return;
    int l4 = lane >> 2, lm = lane & 3;
    unsigned a0[8], a1[8];
    {
        const unsigned* A0 = V1 + ((rb + l4) << 5) + lm;
        const unsigned* A1 = V1 + ((rb + l4 + 8) << 5) + lm;
#pragma unroll
        for (int t = 0; t < 8; t++) { a0[t] = A0[4 * t]; a1[t] = A1[4 * t]; }
    }
    float ssum0 = 0.f, ssum1 = 0.f;
#pragma unroll
    for (int nt = 0; nt < 4; nt++) {
        int col0 = cb + nt * 8;
        unsigned b[8];
        const unsigned* B0 = V2 + ((col0 + l4) << 5) + lm;
#pragma unroll
        for (int t = 0; t < 8; t++) b[t] = B0[4 * t];
        float c0 = 0.f, c1 = 0.f, c2 = 0.f, c3 = 0.f;
#pragma unroll
        for (int kb = 0; kb < 4; kb++) {
            asm volatile(
                "mma.sync.aligned.m16n8k16.row.col.f32.f16.f16.f32 "
                "{%0,%1,%2,%3}, {%4,%5,%6,%7}, {%8,%9}, {%0,%1,%2,%3};"
                : "+f"(c0), "+f"(c1), "+f"(c2), "+f"(c3)
                : "r"(a0[2 * kb]), "r"(a1[2 * kb]),
                  "r"(a0[2 * kb + 1]), "r"(a1[2 * kb + 1]),
                  "r"(b[2 * kb]), "r"(b[2 * kb + 1]));
        }
        int cA = col0 + lm * 2, cB = cA + 1;
        if (cA < U) { ssum0 += fexp(fmaf(c0, INV_TEMP, -5.0f));
                      ssum1 += fexp(fmaf(c2, INV_TEMP, -5.0f)); }
        if (cB < U) { ssum0 += fexp(fmaf(c1, INV_TEMP, -5.0f));
                      ssum1 += fexp(fmaf(c3, INV_TEMP, -5.0f)); }
    }
#pragma unroll
    for (int o = 1; o < 4; o <<= 1) {
        ssum0 += __shfl_xor_sync(0xffffffffu, ssum0, o);
        ssum1 += __shfl_xor_sync(0xffffffffu, ssum1, o);
    }
    if (lm == 0) {
        if (rb + l4 < U)     atomicAdd(&S[rb + l4], ssum0);
        if (rb + l4 + 8 < U) atomicAdd(&S[rb + l4 + 8], ssum1);
    }
}

// ---------------- NCE finalize + output (single block) ----------------
__global__ void __launch_bounds__(256) k_final(float* out) {
    int tid = threadIdx.x;
    int lane = tid & 31, warp = tid >> 5;
    float cU = 0.f, cI = 0.f;
    int Uu = g_ucnt, Ui = g_icnt;
    for (int i = tid; i < 2 * BATCHC; i += 256) {
        int which = (i >= BATCHC);
        int j = i - which * BATCHC;
        int U = which ? Ui : Uu;
        if (j < U) {
            float c = 5.0f + logf(g_S[i]) - (which ? g_posI[j] : g_posU[j]);
            if (which) cI += c; else cU += c;
        }
    }
    cU = wredsum(cU);
    cI = wredsum(cI);
    __shared__ float sU[8], sI[8];
    if (lane == 0) { sU[warp] = cU; sI[warp] = cI; }
    __syncthreads();
    if (tid == 0) {
        float tU = 0.f, tI = 0.f;
        for (int w = 0; w < 8; w++) { tU += sU[w]; tI += sI[w]; }
        float rec = g_acc[0] / (float)BATCHC;
        float reg = 1e-4f * (sqrtf(g_acc[1]) + sqrtf(g_acc[2]));
        float cl = 0.2f * (tU / (float)Uu + tI / (float)Ui);
        out[0] = rec + reg + cl;
        out[1] = cl;
    }
}

// ---------------- launch ----------------
extern "C" void kernel_launch(void* const* d_in, const int* in_sizes, int n_in,
                              void* d_out, int out_size) {
    const float* ue = (const float*)d_in[0];
    const float* ie = (const float*)d_in[1];
    const float* av = (const float*)d_in[2];
    const int*   ar = (const int*)d_in[3];
    const int*   ac = (const int*)d_in[4];
    const int*   ul = (const int*)d_in[5];
    const int*   pl = (const int*)d_in[6];
    const int*   nl = (const int*)d_in[7];
    float* out = (float*)d_out;

    const int SCAN_BLOCKS = (N_NODESC + 1023) / 1024;
    const int PAIRED_BLOCKS = NPAIR / 4;

    unsigned seeds[2] = {101u, 202u};
    unsigned fk[2][3][2];
    for (int vv = 0; vv < 2; vv++)
        for (int k = 0; k < 3; k++)
            tf2x32(0u, seeds[vv], 0u, (unsigned)k, fk[vv][k][0], fk[vv][k][1]);

    k_init<<<(N_NODESC + 255) / 256, 256>>>();
    k_hist<<<(NNZC + 255) / 256, 256>>>(ar);
    k_scan1<<<SCAN_BLOCKS, 1024>>>();
    k_scan2<<<1, 256>>>(SCAN_BLOCKS);
    k_scan3<<<SCAN_BLOCKS, 1024>>>();
    k_fill<<<(NNZC + 255) / 256, 256>>>(ar, ac, av);
    k_unique2<<<(2 * BATCHC + 255) / 256, 256>>>(ul, pl);

    k_spmm_e1_noise<<<PAIRED_BLOCKS, 256>>>(ue, ie,
        fk[0][0][0], fk[0][0][1], fk[1][0][0], fk[1][0][1]);
    k_spmm_l2<<<PAIRED_BLOCKS, 256>>>(fk[0][1][0], fk[0][1][1], fk[1][1][0], fk[1][1][1]);
    k_bpr<<<(BATCHC * 32) / 256, 256>>>(ul, pl, nl);
    k_vfinal<<<(2 * BATCHC * 32) / 256, 256>>>(fk[0][2][0], fk[0][2][1], fk[1][2][0], fk[1][2][1]);

    dim3 nce_grid(BATCHC / 32, BATCHC / 128, 2);
    k_nce<<<nce_grid, 256>>>();
    k_final<<<1, 256>>>(out);
}

// round 16
// speedup vs baseline: 1.2565x; 1.0375x over previous
#include <cuda_runtime.h>
#include <cuda_fp16.h>
#include <cstdint>

#define N_USERS 100000
#define N_ITEMS 50000
#define N_NODESC 150000
#define NNZC 2400000
#define DIM 64
#define BATCHC 4096
#define HALFC 4800000u
#define NPAIR 75000
#define EPSC 0.1f
#define INV_TEMP 5.0f

// ---------------- static device scratch (allocation-free) ----------------
__device__ unsigned g_inh[N_NODESC * 32]; // fp16-staged inputs: half2(col 2l, 2l+1) at [row*32+l]
__device__ uint4  g_c1 [N_NODESC * 32];   // {e1x, e1y (fp32 bits), d1 half4}
__device__ uint4  g_c2 [N_NODESC * 32];   // {e2x, e2y (fp32 bits), d2 half4}
__device__ int2   g_cv[NNZC];
__device__ int    g_rowptr[N_NODESC + 1];
__device__ int    g_cursor[N_NODESC];
__device__ int    g_counts[N_NODESC];
__device__ int    g_blocksums[256];
__device__ int    g_flags[N_NODESC];
__device__ int    g_uidx[BATCHC];
__device__ int    g_iidx[BATCHC];
__device__ int    g_ucnt;
__device__ int    g_icnt;
__device__ unsigned g_Vh[4][BATCHC * 32]; // half2-packed normalized views
__device__ float  g_posU[BATCHC], g_posI[BATCHC];
__device__ float  g_S[2 * BATCHC];
__device__ float  g_acc[8];               // 0 rec, 1 ssu, 2 ssp

// ---------------- half pack/unpack ----------------
__device__ __forceinline__ uint2 pack4h(float a, float b, float c, float d) {
    __half2 lo = __floats2half2_rn(a, b);
    __half2 hi = __floats2half2_rn(c, d);
    uint2 r;
    r.x = *(const unsigned*)&lo;
    r.y = *(const unsigned*)&hi;
    return r;
}
__device__ __forceinline__ float4 unpack4h2(unsigned lo, unsigned hi) {
    float2 l = __half22float2(*(const __half2*)&lo);
    float2 h = __half22float2(*(const __half2*)&hi);
    return make_float4(l.x, l.y, h.x, h.y);
}
__device__ __forceinline__ unsigned pack2h(float a, float b) {
    __half2 h = __floats2half2_rn(a, b);
    return *(const unsigned*)&h;
}
__device__ __forceinline__ float2 unpack2h(unsigned u) {
    return __half22float2(*(const __half2*)&u);
}

// ---------------- threefry-2x32 (exact JAX schedule) ----------------
__host__ __device__ __forceinline__ unsigned rl32(unsigned x, int r) {
    return (x << r) | (x >> (32 - r));
}
__host__ __device__ __forceinline__ void tf2x32(unsigned k0, unsigned k1,
                                                unsigned x0, unsigned x1,
                                                unsigned& o0, unsigned& o1) {
    unsigned k2 = k0 ^ k1 ^ 0x1BD11BDAu;
    x0 += k0; x1 += k1;
#define TFR(r) { x0 += x1; x1 = rl32(x1, r); x1 ^= x0; }
    TFR(13) TFR(15) TFR(26) TFR(6)
    x0 += k1; x1 += k2 + 1u;
    TFR(17) TFR(29) TFR(16) TFR(24)
    x0 += k2; x1 += k0 + 2u;
    TFR(13) TFR(15) TFR(26) TFR(6)
    x0 += k0; x1 += k1 + 3u;
    TFR(17) TFR(29) TFR(16) TFR(24)
    x0 += k1; x1 += k2 + 4u;
    TFR(13) TFR(15) TFR(26) TFR(6)
    x0 += k2; x1 += k0 + 5u;
#undef TFR
    o0 = x0; o1 = x1;
}
__device__ __forceinline__ float u32_to_unit(unsigned b) {
    return __uint_as_float((b >> 9) | 0x3f800000u) - 1.0f;
}
__device__ __forceinline__ float wredsum(float v) {
#pragma unroll
    for (int o = 16; o; o >>= 1) v += __shfl_xor_sync(0xffffffffu, v, o);
    return v;
}
__device__ __forceinline__ float sgn(float x) {
    return (x > 0.f) ? 1.f : ((x < 0.f) ? -1.f : 0.f);
}
// FMA-only exp for x in [-15, 0]
__device__ __forceinline__ float fexp(float x) {
    float t = x * 1.4426950408889634f;
    float fi = floorf(t);
    float f = t - fi;
    float p = 1.5404e-4f;
    p = fmaf(p, f, 1.3333558e-3f);
    p = fmaf(p, f, 9.6181291e-3f);
    p = fmaf(p, f, 5.5504109e-2f);
    p = fmaf(p, f, 2.4022651e-1f);
    p = fmaf(p, f, 6.9314718e-1f);
    p = fmaf(p, f, 1.0f);
    return __int_as_float(((int)fi + 127) << 23) * p;
}

// per-row noise for standalone rows
__device__ __forceinline__ void row_noise(int row, int lane, unsigned k0, unsigned k1,
                                          float& nx, float& ny, float& sc) {
    int half = (row >= NPAIR);
    unsigned base = (unsigned)(half ? row - NPAIR : row) * 64u + (unsigned)(lane * 2);
    unsigned a0, a1, b0, b1;
    tf2x32(k0, k1, base, base + HALFC, a0, a1);
    tf2x32(k0, k1, base + 1u, base + 1u + HALFC, b0, b1);
    nx = u32_to_unit(half ? a1 : a0);
    ny = u32_to_unit(half ? b1 : b0);
    sc = EPSC * rsqrtf(wredsum(nx * nx + ny * ny));
}

// layer-1 gather from fp16-staged inputs: ONE 4B LDG per nnz/lane
__device__ __forceinline__ float2 csr_row_inh(int row, int lane) {
    int s = g_rowptr[row], e = g_rowptr[row + 1];
    float ax = 0.f, ay = 0.f, bx = 0.f, by = 0.f;
    float cx = 0.f, cy = 0.f, dx = 0.f, dy = 0.f;
    int i = s;
    for (; i + 3 < e; i += 4) {
        int2 c0 = g_cv[i], c1 = g_cv[i + 1], c2 = g_cv[i + 2], c3 = g_cv[i + 3];
        unsigned h0 = g_inh[(c0.x << 5) + lane];
        unsigned h1 = g_inh[(c1.x << 5) + lane];
        unsigned h2 = g_inh[(c2.x << 5) + lane];
        unsigned h3 = g_inh[(c3.x << 5) + lane];
        float v0 = __int_as_float(c0.y), v1 = __int_as_float(c1.y);
        float v2 = __int_as_float(c2.y), v3 = __int_as_float(c3.y);
        float2 p0 = unpack2h(h0), p1 = unpack2h(h1), p2 = unpack2h(h2), p3 = unpack2h(h3);
        ax = fmaf(v0, p0.x, ax); ay = fmaf(v0, p0.y, ay);
        bx = fmaf(v1, p1.x, bx); by = fmaf(v1, p1.y, by);
        cx = fmaf(v2, p2.x, cx); cy = fmaf(v2, p2.y, cy);
        dx = fmaf(v3, p3.x, dx); dy = fmaf(v3, p3.y, dy);
    }
    for (; i < e; i++) {
        int2 c0 = g_cv[i];
        float2 p0 = unpack2h(g_inh[(c0.x << 5) + lane]);
        float v0 = __int_as_float(c0.y);
        ax = fmaf(v0, p0.x, ax); ay = fmaf(v0, p0.y, ay);
    }
    return make_float2((ax + bx) + (cx + dx), (ay + by) + (cy + dy));
}

// one CSR pass over c1 (AoS 16B): se = A*e1, sd = A*d1
__device__ __forceinline__ void csr_row_l2(int row, int lane, float2& se, float4& sd) {
    int s = g_rowptr[row], e = g_rowptr[row + 1];
    float ex0 = 0.f, ey0 = 0.f, ex1 = 0.f, ey1 = 0.f;
    float dx0 = 0.f, dy0 = 0.f, dz0 = 0.f, dw0 = 0.f;
    float dx1 = 0.f, dy1 = 0.f, dz1 = 0.f, dw1 = 0.f;
    int i = s;
    for (; i + 3 < e; i += 4) {
        int2 c0 = g_cv[i], c1 = g_cv[i + 1], c2 = g_cv[i + 2], c3 = g_cv[i + 3];
        uint4 u0 = g_c1[(c0.x << 5) + lane];
        uint4 u1 = g_c1[(c1.x << 5) + lane];
        uint4 u2 = g_c1[(c2.x << 5) + lane];
        uint4 u3 = g_c1[(c3.x << 5) + lane];
        float v0 = __int_as_float(c0.y), v1 = __int_as_float(c1.y);
        float v2 = __int_as_float(c2.y), v3 = __int_as_float(c3.y);
        float4 p0 = unpack4h2(u0.z, u0.w), p1 = unpack4h2(u1.z, u1.w);
        float4 p2 = unpack4h2(u2.z, u2.w), p3 = unpack4h2(u3.z, u3.w);
        ex0 = fmaf(v0, __int_as_float(u0.x), ex0); ey0 = fmaf(v0, __int_as_float(u0.y), ey0);
        ex1 = fmaf(v1, __int_as_float(u1.x), ex1); ey1 = fmaf(v1, __int_as_float(u1.y), ey1);
        ex0 = fmaf(v2, __int_as_float(u2.x), ex0); ey0 = fmaf(v2, __int_as_float(u2.y), ey0);
        ex1 = fmaf(v3, __int_as_float(u3.x), ex1); ey1 = fmaf(v3, __int_as_float(u3.y), ey1);
        dx0 = fmaf(v0, p0.x, dx0); dy0 = fmaf(v0, p0.y, dy0);
        dz0 = fmaf(v0, p0.z, dz0); dw0 = fmaf(v0, p0.w, dw0);
        dx1 = fmaf(v1, p1.x, dx1); dy1 = fmaf(v1, p1.y, dy1);
        dz1 = fmaf(v1, p1.z, dz1); dw1 = fmaf(v1, p1.w, dw1);
        dx0 = fmaf(v2, p2.x, dx0); dy0 = fmaf(v2, p2.y, dy0);
        dz0 = fmaf(v2, p2.z, dz0); dw0 = fmaf(v2, p2.w, dw0);
        dx1 = fmaf(v3, p3.x, dx1); dy1 = fmaf(v3, p3.y, dy1);
        dz1 = fmaf(v3, p3.z, dz1); dw1 = fmaf(v3, p3.w, dw1);
    }
    for (; i < e; i++) {
        int2 c0 = g_cv[i];
        uint4 u0 = g_c1[(c0.x << 5) + lane];
        float4 p0 = unpack4h2(u0.z, u0.w);
        float v0 = __int_as_float(c0.y);
        ex0 = fmaf(v0, __int_as_float(u0.x), ex0); ey0 = fmaf(v0, __int_as_float(u0.y), ey0);
        dx0 = fmaf(v0, p0.x, dx0); dy0 = fmaf(v0, p0.y, dy0);
        dz0 = fmaf(v0, p0.z, dz0); dw0 = fmaf(v0, p0.w, dw0);
    }
    se = make_float2(ex0 + ex1, ey0 + ey1);
    sd = make_float4(dx0 + dx1, dy0 + dy1, dz0 + dz1, dw0 + dw1);
}

// BPR layer-3: gather e2 only from c2 (8B of the 16B record)
__device__ __forceinline__ float2 csr_row_e2(int row, int lane) {
    int s = g_rowptr[row], e = g_rowptr[row + 1];
    float ax = 0.f, ay = 0.f, bx = 0.f, by = 0.f;
    float cx = 0.f, cy = 0.f, dx = 0.f, dy = 0.f;
    int i = s;
    for (; i + 3 < e; i += 4) {
        int2 c0 = g_cv[i], c1 = g_cv[i + 1], c2 = g_cv[i + 2], c3 = g_cv[i + 3];
        uint2 q0 = *(const uint2*)&g_c2[(c0.x << 5) + lane];
        uint2 q1 = *(const uint2*)&g_c2[(c1.x << 5) + lane];
        uint2 q2 = *(const uint2*)&g_c2[(c2.x << 5) + lane];
        uint2 q3 = *(const uint2*)&g_c2[(c3.x << 5) + lane];
        float v0 = __int_as_float(c0.y), v1 = __int_as_float(c1.y);
        float v2 = __int_as_float(c2.y), v3 = __int_as_float(c3.y);
        ax = fmaf(v0, __int_as_float(q0.x), ax); ay = fmaf(v0, __int_as_float(q0.y), ay);
        bx = fmaf(v1, __int_as_float(q1.x), bx); by = fmaf(v1, __int_as_float(q1.y), by);
        cx = fmaf(v2, __int_as_float(q2.x), cx); cy = fmaf(v2, __int_as_float(q2.y), cy);
        dx = fmaf(v3, __int_as_float(q3.x), dx); dy = fmaf(v3, __int_as_float(q3.y), dy);
    }
    for (; i < e; i++) {
        int2 c0 = g_cv[i];
        uint2 q0 = *(const uint2*)&g_c2[(c0.x << 5) + lane];
        float v0 = __int_as_float(c0.y);
        ax = fmaf(v0, __int_as_float(q0.x), ax); ay = fmaf(v0, __int_as_float(q0.y), ay);
    }
    return make_float2((ax + bx) + (cx + dx), (ay + by) + (cy + dy));
}

// layer-3 view gather: A*(e2 + d2) for one row, both views
__device__ __forceinline__ float4 csr_row_l3(int row, int lane) {
    int s = g_rowptr[row], e = g_rowptr[row + 1];
    float ax = 0.f, ay = 0.f, az = 0.f, aw = 0.f;
    float bx = 0.f, by = 0.f, bz = 0.f, bw = 0.f;
    int i = s;
    for (; i + 1 < e; i += 2) {
        int2 c0 = g_cv[i], c1 = g_cv[i + 1];
        uint4 u0 = g_c2[(c0.x << 5) + lane];
        uint4 u1 = g_c2[(c1.x << 5) + lane];
        float4 p0 = unpack4h2(u0.z, u0.w);
        float4 p1 = unpack4h2(u1.z, u1.w);
        float e0x = __int_as_float(u0.x), e0y = __int_as_float(u0.y);
        float e1x = __int_as_float(u1.x), e1y = __int_as_float(u1.y);
        float v0 = __int_as_float(c0.y), v1 = __int_as_float(c1.y);
        ax = fmaf(v0, e0x + p0.x, ax); ay = fmaf(v0, e0y + p0.y, ay);
        az = fmaf(v0, e0x + p0.z, az); aw = fmaf(v0, e0y + p0.w, aw);
        bx = fmaf(v1, e1x + p1.x, bx); by = fmaf(v1, e1y + p1.y, by);
        bz = fmaf(v1, e1x + p1.z, bz); bw = fmaf(v1, e1y + p1.w, bw);
    }
    if (i < e) {
        int2 c0 = g_cv[i];
        uint4 u0 = g_c2[(c0.x << 5) + lane];
        float4 p0 = unpack4h2(u0.z, u0.w);
        float e0x = __int_as_float(u0.x), e0y = __int_as_float(u0.y);
        float v0 = __int_as_float(c0.y);
        ax = fmaf(v0, e0x + p0.x, ax); ay = fmaf(v0, e0y + p0.y, ay);
        az = fmaf(v0, e0x + p0.z, az); aw = fmaf(v0, e0y + p0.w, aw);
    }
    return make_float4(ax + bx, ay + by, az + bz, aw + bw);
}

// ---------------- setup (also stages inputs to fp16) ----------------
__global__ void k_init(const float* __restrict__ ue, const float* __restrict__ ie) {
    int i = blockIdx.x * blockDim.x + threadIdx.x;
    if (i < N_NODESC * 32) {
        int row = i >> 5, lane = i & 31;
        float2 v = (row < N_USERS)
            ? ((const float2*)(ue + (row << 6)))[lane]
            : ((const float2*)(ie + ((row - N_USERS) << 6)))[lane];
        g_inh[i] = pack2h(v.x, v.y);
    }
    if (i < N_NODESC) { g_flags[i] = 0; g_counts[i] = 0; }
    if (i < 2 * BATCHC) g_S[i] = 0.f;
    if (i < 8) g_acc[i] = 0.f;
    if (i == 0) { g_ucnt = 0; g_icnt = 0; }
}
__global__ void k_hist(const int* __restrict__ rows) {
    int i = blockIdx.x * blockDim.x + threadIdx.x;
    if (i < NNZC) atomicAdd(&g_counts[rows[i]], 1);
}
__global__ void k_scan1() {
    __shared__ int sh[1024];
    int g = blockIdx.x * 1024 + threadIdx.x;
    int v = (g < N_NODESC) ? g_counts[g] : 0;
    sh[threadIdx.x] = v;
    __syncthreads();
    for (int off = 1; off < 1024; off <<= 1) {
        int t = (threadIdx.x >= off) ? sh[threadIdx.x - off] : 0;
        __syncthreads();
        sh[threadIdx.x] += t;
        __syncthreads();
    }
    if (g < N_NODESC) g_rowptr[g] = sh[threadIdx.x] - v;
    if (threadIdx.x == 1023) g_blocksums[blockIdx.x] = sh[1023];
}
__global__ void k_scan2(int nblocks) {
    __shared__ int sh[256];
    int t = threadIdx.x;
    int v = (t < nblocks) ? g_blocksums[t] : 0;
    sh[t] = v;
    __syncthreads();
    for (int off = 1; off < 256; off <<= 1) {
        int p = (t >= off) ? sh[t - off] : 0;
        __syncthreads();
        sh[t] += p;
        __syncthreads();
    }
    if (t < nblocks) g_blocksums[t] = sh[t] - v;
    if (t == nblocks - 1) g_rowptr[N_NODESC] = sh[t];
}
__global__ void k_scan3() {
    int g = blockIdx.x * blockDim.x + threadIdx.x;
    if (g < N_NODESC) {
        int v = g_rowptr[g] + g_blocksums[g >> 10];
        g_rowptr[g] = v;
        g_cursor[g] = v;
    }
}
__global__ void k_fill(const int* __restrict__ rows, const int* __restrict__ cols,
                       const float* __restrict__ vals) {
    int i = blockIdx.x * blockDim.x + threadIdx.x;
    if (i < NNZC) {
        int p = atomicAdd(&g_cursor[rows[i]], 1);
        g_cv[p] = make_int2(cols[i], __float_as_int(vals[i]));
    }
}

// ---------------- layer 1: c1 = {e1 = A*inh, d1 = noise offsets} (paired tf) ----------------
__global__ void __launch_bounds__(256) k_spmm_e1_noise(unsigned f10, unsigned f11,
                                                       unsigned f20, unsigned f21) {
    int warp = threadIdx.x >> 5;
    int lane = threadIdx.x & 31;
    int sub = warp & 3;
    int hi = warp >> 2;
    int pr = blockIdx.x * 4 + sub;
    int row = pr + hi * NPAIR;
    __shared__ unsigned shn[2][4][32][2];
    float2 ea = csr_row_inh(row, lane);
    unsigned myx[2], myy[2];
    if (!hi) {
        unsigned base = (unsigned)pr * 64u + (unsigned)(lane * 2);
#pragma unroll
        for (int vv = 0; vv < 2; vv++) {
            unsigned k0 = vv ? f20 : f10, k1 = vv ? f21 : f11;
            unsigned a0, a1, b0, b1;
            tf2x32(k0, k1, base, base + HALFC, a0, a1);
            tf2x32(k0, k1, base + 1u, base + 1u + HALFC, b0, b1);
            myx[vv] = a0; myy[vv] = b0;
            shn[vv][sub][lane][0] = a1;
            shn[vv][sub][lane][1] = b1;
        }
    }
    __syncthreads();
    if (hi) {
#pragma unroll
        for (int vv = 0; vv < 2; vv++) {
            myx[vv] = shn[vv][sub][lane][0];
            myy[vv] = shn[vv][sub][lane][1];
        }
    }
    float o1x, o1y, o2x, o2y;
    {
        float nx = u32_to_unit(myx[0]), ny = u32_to_unit(myy[0]);
        float sc = EPSC * rsqrtf(wredsum(nx * nx + ny * ny));
        o1x = sgn(ea.x) * nx * sc;
        o1y = sgn(ea.y) * ny * sc;
    }
    {
        float nx = u32_to_unit(myx[1]), ny = u32_to_unit(myy[1]);
        float sc = EPSC * rsqrtf(wredsum(nx * nx + ny * ny));
        o2x = sgn(ea.x) * nx * sc;
        o2y = sgn(ea.y) * ny * sc;
    }
    uint2 dh = pack4h(o1x, o1y, o2x, o2y);
    g_c1[(row << 5) + lane] = make_uint4(__float_as_int(ea.x), __float_as_int(ea.y), dh.x, dh.y);
}

// ---------------- layer 2: c2 = {e2 = A*e1, d2 = A*d1 + noise2} (paired tf) ----------------
__global__ void __launch_bounds__(256) k_spmm_l2(unsigned f10, unsigned f11,
                                                 unsigned f20, unsigned f21) {
    int warp = threadIdx.x >> 5;
    int lane = threadIdx.x & 31;
    int sub = warp & 3;
    int hi = warp >> 2;
    int pr = blockIdx.x * 4 + sub;
    int row = pr + hi * NPAIR;
    __shared__ unsigned shn[2][4][32][2];
    float2 se;
    float4 sd;
    csr_row_l2(row, lane, se, sd);
    unsigned myx[2], myy[2];
    if (!hi) {
        unsigned base = (unsigned)pr * 64u + (unsigned)(lane * 2);
#pragma unroll
        for (int vv = 0; vv < 2; vv++) {
            unsigned k0 = vv ? f20 : f10, k1 = vv ? f21 : f11;
            unsigned a0, a1, b0, b1;
            tf2x32(k0, k1, base, base + HALFC, a0, a1);
            tf2x32(k0, k1, base + 1u, base + 1u + HALFC, b0, b1);
            myx[vv] = a0; myy[vv] = b0;
            shn[vv][sub][lane][0] = a1;
            shn[vv][sub][lane][1] = b1;
        }
    }
    __syncthreads();
    if (hi) {
#pragma unroll
        for (int vv = 0; vv < 2; vv++) {
            myx[vv] = shn[vv][sub][lane][0];
            myy[vv] = shn[vv][sub][lane][1];
        }
    }
    float y1x = se.x + sd.x, y1y = se.y + sd.y;
    float y2x = se.x + sd.z, y2y = se.y + sd.w;
    {
        float nx = u32_to_unit(myx[0]), ny = u32_to_unit(myy[0]);
        float sc = EPSC * rsqrtf(wredsum(nx * nx + ny * ny));
        sd.x += sgn(y1x) * nx * sc;
        sd.y += sgn(y1y) * ny * sc;
    }
    {
        float nx = u32_to_unit(myx[1]), ny = u32_to_unit(myy[1]);
        float sc = EPSC * rsqrtf(wredsum(nx * nx + ny * ny));
        sd.z += sgn(y2x) * nx * sc;
        sd.w += sgn(y2y) * ny * sc;
    }
    uint2 dh = pack4h(sd.x, sd.y, sd.z, sd.w);
    g_c2[(row << 5) + lane] = make_uint4(__float_as_int(se.x), __float_as_int(se.y), dh.x, dh.y);
}

// ---------------- order-free unique (both lists in one launch) ----------------
__global__ void k_unique2(const int* __restrict__ ul, const int* __restrict__ pl) {
    int i = blockIdx.x * blockDim.x + threadIdx.x;
    if (i >= 2 * BATCHC) return;
    int which = (i >= BATCHC);
    int j = which ? i - BATCHC : i;
    int v = which ? pl[j] : ul[j];
    int fidx = which ? (N_USERS + v) : v;
    if (atomicExch(&g_flags[fidx], 1) == 0) {
        int p = atomicAdd(which ? &g_icnt : &g_ucnt, 1);
        (which ? g_iidx : g_uidx)[p] = v;
    }
}

// ---------------- merged BPR + view-finalize (one launch; 3*BATCH warps) ----------------
__global__ void __launch_bounds__(256) k_bprvf(const int* __restrict__ ul,
                                               const int* __restrict__ pl,
                                               const int* __restrict__ nl,
                                               unsigned f10, unsigned f11,
                                               unsigned f20, unsigned f21) {
    int w = (blockIdx.x * blockDim.x + threadIdx.x) >> 5;
    int lane = threadIdx.x & 31;
    if (w < BATCHC) {
        // ---- BPR ----
        const float third = 1.f / 3.f;
        int ru = ul[w];
        int rp = N_USERS + pl[w];
        int rn = N_USERS + nl[w];
        float2 u3 = csr_row_e2(ru, lane);
        float2 p3 = csr_row_e2(rp, lane);
        float2 n3 = csr_row_e2(rn, lane);
        uint4 uc1 = g_c1[(ru << 5) + lane], uc2 = g_c2[(ru << 5) + lane];
        uint4 pc1 = g_c1[(rp << 5) + lane], pc2 = g_c2[(rp << 5) + lane];
        uint4 nc1 = g_c1[(rn << 5) + lane], nc2 = g_c2[(rn << 5) + lane];
        float ux = (__int_as_float(uc1.x) + __int_as_float(uc2.x) + u3.x) * third;
        float uy = (__int_as_float(uc1.y) + __int_as_float(uc2.y) + u3.y) * third;
        float px = (__int_as_float(pc1.x) + __int_as_float(pc2.x) + p3.x) * third;
        float py = (__int_as_float(pc1.y) + __int_as_float(pc2.y) + p3.y) * third;
        float nx = (__int_as_float(nc1.x) + __int_as_float(nc2.x) + n3.x) * third;
        float ny = (__int_as_float(nc1.y) + __int_as_float(nc2.y) + n3.y) * third;
        float pos = wredsum(ux * px + uy * py);
        float neg = wredsum(ux * nx + uy * ny);
        float ssu = wredsum(ux * ux + uy * uy);
        float ssp = wredsum(px * px + py * py);
        if (lane == 0) {
            float d = pos - neg;
            float sig = 1.f / (1.f + expf(-d));
            atomicAdd(&g_acc[0], -logf(1e-7f + sig));
            atomicAdd(&g_acc[1], ssu);
            atomicAdd(&g_acc[2], ssp);
        }
        return;
    }
    // ---- view finalize ----
    int wv = w - BATCHC;
    int isItem = (wv >= BATCHC);
    int j = isItem ? wv - BATCHC : wv;
    int cnt = isItem ? g_icnt : g_ucnt;
    if (j >= cnt) return;
    int row = isItem ? (N_USERS + g_iidx[j]) : g_uidx[j];
    float4 a3 = csr_row_l3(row, lane);
    float nx, ny, sc;
    row_noise(row, lane, f10, f11, nx, ny, sc);
    a3.x += sgn(a3.x) * nx * sc;
    a3.y += sgn(a3.y) * ny * sc;
    row_noise(row, lane, f20, f21, nx, ny, sc);
    a3.z += sgn(a3.z) * nx * sc;
    a3.w += sgn(a3.w) * ny * sc;
    uint4 c1r = g_c1[(row << 5) + lane];
    uint4 c2r = g_c2[(row << 5) + lane];
    float e1x = __int_as_float(c1r.x), e1y = __int_as_float(c1r.y);
    float e2x = __int_as_float(c2r.x), e2y = __int_as_float(c2r.y);
    float4 d1r = unpack4h2(c1r.z, c1r.w);
    float4 d2r = unpack4h2(c2r.z, c2r.w);
    float s1x = (e1x + d1r.x) + (e2x + d2r.x) + a3.x;
    float s1y = (e1y + d1r.y) + (e2y + d2r.y) + a3.y;
    float inv1 = rsqrtf(wredsum(s1x * s1x + s1y * s1y));
    s1x *= inv1; s1y *= inv1;
    float s2x = (e1x + d1r.z) + (e2x + d2r.z) + a3.z;
    float s2y = (e1y + d1r.w) + (e2y + d2r.w) + a3.w;
    float inv2 = rsqrtf(wredsum(s2x * s2x + s2y * s2y));
    s2x *= inv2; s2y *= inv2;
    g_Vh[0 * 2 + isItem][(j << 5) + lane] = pack2h(s1x, s1y);
    g_Vh[1 * 2 + isItem][(j << 5) + lane] = pack2h(s2x, s2y);
    float d = wredsum(s2x * s1x + s2y * s1y);
    if (lane == 0) (isItem ? g_posI : g_posU)[j] = d * INV_TEMP;
}

// ---------------- InfoNCE via mma.sync (HMMA): warp = m16 x n32 tile ----------------
__global__ void __launch_bounds__(256) k_nce() {
    int which = blockIdx.z;
    const unsigned* __restrict__ V1 = g_Vh[0 * 2 + which];
    const unsigned* __restrict__ V2 = g_Vh[1 * 2 + which];
    float* __restrict__ S = g_S + which * BATCHC;
    int U = which ? g_icnt : g_ucnt;
    int warp = threadIdx.x >> 5;
    int lane = threadIdx.x & 31;
    int rb = blockIdx.y * 128 + warp * 16;
    int cb = blockIdx.x * 32;
    if (rb >= U || cb >= U) return;
    int l4 = lane >> 2, lm = lane & 3;
    unsigned a0[8], a1[8];
    {
        const unsigned* A0 = V1 + ((rb + l4) << 5) + lm;
        const unsigned* A1 = V1 + ((rb + l4 + 8) << 5) + lm;
#pragma unroll
        for (int t = 0; t < 8; t++) { a0[t] = A0[4 * t]; a1[t] = A1[4 * t]; }
    }
    float ssum0 = 0.f, ssum1 = 0.f;
#pragma unroll
    for (int nt = 0; nt < 4; nt++) {
        int col0 = cb + nt * 8;
        unsigned b[8];
        const unsigned* B0 = V2 + ((col0 + l4) << 5) + lm;
#pragma unroll
        for (int t = 0; t < 8; t++) b[t] = B0[4 * t];
        float c0 = 0.f, c1 = 0.f, c2 = 0.f, c3 = 0.f;
#pragma unroll
        for (int kb = 0; kb < 4; kb++) {
            asm volatile(
                "mma.sync.aligned.m16n8k16.row.col.f32.f16.f16.f32 "
                "{%0,%1,%2,%3}, {%4,%5,%6,%7}, {%8,%9}, {%0,%1,%2,%3};"
                : "+f"(c0), "+f"(c1), "+f"(c2), "+f"(c3)
                : "r"(a0[2 * kb]), "r"(a1[2 * kb]),
                  "r"(a0[2 * kb + 1]), "r"(a1[2 * kb + 1]),
                  "r"(b[2 * kb]), "r"(b[2 * kb + 1]));
        }
        int cA = col0 + lm * 2, cB = cA + 1;
        if (cA < U) { ssum0 += fexp(fmaf(c0, INV_TEMP, -5.0f));
                      ssum1 += fexp(fmaf(c2, INV_TEMP, -5.0f)); }
        if (cB < U) { ssum0 += fexp(fmaf(c1, INV_TEMP, -5.0f));
                      ssum1 += fexp(fmaf(c3, INV_TEMP, -5.0f)); }
    }
#pragma unroll
    for (int o = 1; o < 4; o <<= 1) {
        ssum0 += __shfl_xor_sync(0xffffffffu, ssum0, o);
        ssum1 += __shfl_xor_sync(0xffffffffu, ssum1, o);
    }
    if (lm == 0) {
        if (rb + l4 < U)     atomicAdd(&S[rb + l4], ssum0);
        if (rb + l4 + 8 < U) atomicAdd(&S[rb + l4 + 8], ssum1);
    }
}

// ---------------- NCE finalize + output (single block) ----------------
__global__ void __launch_bounds__(256) k_final(float* out) {
    int tid = threadIdx.x;
    int lane = tid & 31, warp = tid >> 5;
    float cU = 0.f, cI = 0.f;
    int Uu = g_ucnt, Ui = g_icnt;
    for (int i = tid; i < 2 * BATCHC; i += 256) {
        int which = (i >= BATCHC);
        int j = i - which * BATCHC;
        int U = which ? Ui : Uu;
        if (j < U) {
            float c = 5.0f + logf(g_S[i]) - (which ? g_posI[j] : g_posU[j]);
            if (which) cI += c; else cU += c;
        }
    }
    cU = wredsum(cU);
    cI = wredsum(cI);
    __shared__ float sU[8], sI[8];
    if (lane == 0) { sU[warp] = cU; sI[warp] = cI; }
    __syncthreads();
    if (tid == 0) {
        float tU = 0.f, tI = 0.f;
        for (int w = 0; w < 8; w++) { tU += sU[w]; tI += sI[w]; }
        float rec = g_acc[0] / (float)BATCHC;
        float reg = 1e-4f * (sqrtf(g_acc[1]) + sqrtf(g_acc[2]));
        float cl = 0.2f * (tU / (float)Uu + tI / (float)Ui);
        out[0] = rec + reg + cl;
        out[1] = cl;
    }
}

// ---------------- launch ----------------
extern "C" void kernel_launch(void* const* d_in, const int* in_sizes, int n_in,
                              void* d_out, int out_size) {
    const float* ue = (const float*)d_in[0];
    const float* ie = (const float*)d_in[1];
    const float* av = (const float*)d_in[2];
    const int*   ar = (const int*)d_in[3];
    const int*   ac = (const int*)d_in[4];
    const int*   ul = (const int*)d_in[5];
    const int*   pl = (const int*)d_in[6];
    const int*   nl = (const int*)d_in[7];
    float* out = (float*)d_out;

    const int SCAN_BLOCKS = (N_NODESC + 1023) / 1024;
    const int PAIRED_BLOCKS = NPAIR / 4;

    unsigned seeds[2] = {101u, 202u};
    unsigned fk[2][3][2];
    for (int vv = 0; vv < 2; vv++)
        for (int k = 0; k < 3; k++)
            tf2x32(0u, seeds[vv], 0u, (unsigned)k, fk[vv][k][0], fk[vv][k][1]);

    k_init<<<(N_NODESC * 32 + 255) / 256, 256>>>(ue, ie);
    k_hist<<<(NNZC + 255) / 256, 256>>>(ar);
    k_scan1<<<SCAN_BLOCKS, 1024>>>();
    k_scan2<<<1, 256>>>(SCAN_BLOCKS);
    k_scan3<<<SCAN_BLOCKS, 1024>>>();
    k_fill<<<(NNZC + 255) / 256, 256>>>(ar, ac, av);
    k_unique2<<<(2 * BATCHC + 255) / 256, 256>>>(ul, pl);

    k_spmm_e1_noise<<<PAIRED_BLOCKS, 256>>>(
        fk[0][0][0], fk[0][0][1], fk[1][0][0], fk[1][0][1]);
    k_spmm_l2<<<PAIRED_BLOCKS, 256>>>(fk[0][1][0], fk[0][1][1], fk[1][1][0], fk[1][1][1]);
    k_bprvf<<<(3 * BATCHC * 32) / 256, 256>>>(ul, pl, nl,
        fk[0][2][0], fk[0][2][1], fk[1][2][0], fk[1][2][1]);

    dim3 nce_grid(BATCHC / 32, BATCHC / 128, 2);
    k_nce<<<nce_grid, 256>>>();
    k_final<<<1, 256>>>(out);
}